// round 1
// baseline (speedup 1.0000x reference)
#include <cuda_runtime.h>
#include <math.h>

// Problem constants
#define BSZ   2
#define SEQ   2048
#define DIM   1024
#define NH    16
#define HD    64
#define MTOK  (BSZ * SEQ)       // 4096 tokens
#define QKVN  (3 * DIM)         // 3072

// Scratch (no cudaMalloc allowed) — ~66 MB total
__device__ float g_qkv[(size_t)MTOK * QKVN];  // (4096, 3072)
__device__ float g_att[(size_t)MTOK * DIM];   // (4096, 1024)

// ----------------------------------------------------------------------------
// C[M,N] = A[M,K] @ B[N,K]^T   (both operands K-contiguous, row-major)
// 64x64 block tile, 256 threads, 4x4 per thread, BK=16
// ----------------------------------------------------------------------------
__global__ void gemm_abt_kernel(const float* __restrict__ A,
                                const float* __restrict__ B,
                                float* __restrict__ C,
                                int M, int N, int K) {
    __shared__ float As[16][68];
    __shared__ float Bs[16][68];

    const int tid = threadIdx.x;
    const int tx = tid & 15;
    const int ty = tid >> 4;
    const int m0 = blockIdx.y * 64;
    const int n0 = blockIdx.x * 64;

    float acc[4][4];
#pragma unroll
    for (int i = 0; i < 4; i++)
#pragma unroll
        for (int j = 0; j < 4; j++) acc[i][j] = 0.0f;

    for (int k0 = 0; k0 < K; k0 += 16) {
#pragma unroll
        for (int i = 0; i < 4; i++) {
            int e  = tid + i * 256;          // 0..1023
            int r  = e >> 4;                 // 0..63
            int kk = e & 15;                 // 0..15
            As[kk][r] = A[(size_t)(m0 + r) * K + k0 + kk];
            Bs[kk][r] = B[(size_t)(n0 + r) * K + k0 + kk];
        }
        __syncthreads();

#pragma unroll
        for (int kk = 0; kk < 16; kk++) {
            float a[4], b[4];
#pragma unroll
            for (int i = 0; i < 4; i++) a[i] = As[kk][ty * 4 + i];
#pragma unroll
            for (int j = 0; j < 4; j++) b[j] = Bs[kk][tx * 4 + j];
#pragma unroll
            for (int i = 0; i < 4; i++)
#pragma unroll
                for (int j = 0; j < 4; j++) acc[i][j] = fmaf(a[i], b[j], acc[i][j]);
        }
        __syncthreads();
    }

#pragma unroll
    for (int i = 0; i < 4; i++)
#pragma unroll
        for (int j = 0; j < 4; j++)
            C[(size_t)(m0 + ty * 4 + i) * N + n0 + tx * 4 + j] = acc[i][j];
}

// ----------------------------------------------------------------------------
// Causal flash attention, fp32.
// grid: (SEQ/64 query tiles, BSZ*NH). block: 256 threads (16x16 logical).
// Each thread owns a 4x4 tile of S/P (rows=queries, cols=keys) and a 4x4 tile
// of O (rows=queries, cols=head dims). Online softmax with 16-lane shuffles.
// dynamic smem: Qs/Ks/Vs/Ps each [64][65] floats = 66560 B
// ----------------------------------------------------------------------------
#define ATTN_SMEM (4 * 64 * 65 * 4)

__global__ void attn_kernel(const float* __restrict__ qkv,
                            float* __restrict__ att) {
    extern __shared__ float sm[];
    float (*Qs)[65] = (float (*)[65])(sm);
    float (*Ks)[65] = (float (*)[65])(sm + 64 * 65);
    float (*Vs)[65] = (float (*)[65])(sm + 2 * 64 * 65);
    float (*Ps)[65] = (float (*)[65])(sm + 3 * 64 * 65);

    const int tid = threadIdx.x;
    const int tx = tid & 15;
    const int ty = tid >> 4;
    const int bq = blockIdx.x;          // query tile
    const int bh = blockIdx.y;          // batch*head
    const int b  = bh >> 4;
    const int h  = bh & 15;
    const float scale = 0.125f;         // 1/sqrt(64)

    const size_t tok0 = (size_t)b * SEQ;

    // Load Q tile: rows bq*64..+63, head-dim 0..63
#pragma unroll
    for (int i = 0; i < 16; i++) {
        int e = tid + i * 256;          // 0..4095
        int r = e >> 6;
        int d = e & 63;
        Qs[r][d] = qkv[(tok0 + bq * 64 + r) * QKVN + h * HD + d];
    }

    float m[4], l[4], O[4][4];
#pragma unroll
    for (int i = 0; i < 4; i++) {
        m[i] = -INFINITY;
        l[i] = 0.0f;
#pragma unroll
        for (int j = 0; j < 4; j++) O[i][j] = 0.0f;
    }

    const int qr0 = bq * 64 + ty * 4;

    for (int kt = 0; kt <= bq; kt++) {
        __syncthreads();   // prior-iter consumers done; also covers Q load on iter 0

        // Load K/V tiles
#pragma unroll
        for (int i = 0; i < 16; i++) {
            int e = tid + i * 256;
            int r = e >> 6;
            int d = e & 63;
            size_t base = (tok0 + kt * 64 + r) * (size_t)QKVN + h * HD + d;
            Ks[r][d] = qkv[base + DIM];
            Vs[r][d] = qkv[base + 2 * DIM];
        }
        __syncthreads();

        // S = scale * Q K^T  (4x4 per thread)
        float s[4][4];
#pragma unroll
        for (int i = 0; i < 4; i++)
#pragma unroll
            for (int j = 0; j < 4; j++) s[i][j] = 0.0f;

#pragma unroll 8
        for (int dd = 0; dd < 64; dd++) {
            float a[4], bb[4];
#pragma unroll
            for (int i = 0; i < 4; i++) a[i] = Qs[ty * 4 + i][dd];
#pragma unroll
            for (int j = 0; j < 4; j++) bb[j] = Ks[tx * 4 + j][dd];
#pragma unroll
            for (int i = 0; i < 4; i++)
#pragma unroll
                for (int j = 0; j < 4; j++) s[i][j] = fmaf(a[i], bb[j], s[i][j]);
        }

        const int kc0 = kt * 64 + tx * 4;
#pragma unroll
        for (int i = 0; i < 4; i++)
#pragma unroll
            for (int j = 0; j < 4; j++) {
                float v = s[i][j] * scale;
                if (kc0 + j > qr0 + i) v = -INFINITY;   // causal (auto-false for kt<bq)
                s[i][j] = v;
            }

        // Online softmax per row (row spread over 16 lanes of a half-warp)
        float p[4][4];
#pragma unroll
        for (int i = 0; i < 4; i++) {
            float mx = fmaxf(fmaxf(s[i][0], s[i][1]), fmaxf(s[i][2], s[i][3]));
#pragma unroll
            for (int off = 8; off >= 1; off >>= 1)
                mx = fmaxf(mx, __shfl_xor_sync(0xffffffffu, mx, off));
            float mnew = fmaxf(m[i], mx);
            float alpha = __expf(m[i] - mnew);   // m[i]=-inf, mnew finite -> 0

            float rs = 0.0f;
#pragma unroll
            for (int j = 0; j < 4; j++) {
                p[i][j] = __expf(s[i][j] - mnew);
                rs += p[i][j];
            }
#pragma unroll
            for (int off = 8; off >= 1; off >>= 1)
                rs += __shfl_xor_sync(0xffffffffu, rs, off);

            l[i] = l[i] * alpha + rs;
            m[i] = mnew;
#pragma unroll
            for (int j = 0; j < 4; j++) O[i][j] *= alpha;
        }

        // Stage P for the PV GEMM
#pragma unroll
        for (int i = 0; i < 4; i++)
#pragma unroll
            for (int j = 0; j < 4; j++)
                Ps[ty * 4 + i][tx * 4 + j] = p[i][j];
        __syncthreads();

        // O += P @ V  (thread owns rows ty*4.., hd-cols tx*4..)
#pragma unroll 8
        for (int kk = 0; kk < 64; kk++) {
            float a[4], bb[4];
#pragma unroll
            for (int i = 0; i < 4; i++) a[i] = Ps[ty * 4 + i][kk];
#pragma unroll
            for (int j = 0; j < 4; j++) bb[j] = Vs[kk][tx * 4 + j];
#pragma unroll
            for (int i = 0; i < 4; i++)
#pragma unroll
                for (int j = 0; j < 4; j++) O[i][j] = fmaf(a[i], bb[j], O[i][j]);
        }
    }

    // Normalize + write back in (B, T, C) layout: col = h*64 + hd
#pragma unroll
    for (int i = 0; i < 4; i++) {
        float inv = 1.0f / l[i];
#pragma unroll
        for (int j = 0; j < 4; j++)
            att[(tok0 + bq * 64 + ty * 4 + i) * (size_t)DIM + h * HD + tx * 4 + j] =
                O[i][j] * inv;
    }
}

// ----------------------------------------------------------------------------
extern "C" void kernel_launch(void* const* d_in, const int* in_sizes, int n_in,
                              void* d_out, int out_size) {
    const float* x     = (const float*)d_in[0];   // (2, 2048, 1024)
    const float* W_qkv = (const float*)d_in[1];   // (3072, 1024)
    const float* W_out = (const float*)d_in[2];   // (1024, 1024)
    float* out = (float*)d_out;                   // (2, 2048, 1024)

    float *qkv_buf, *att_buf;
    cudaGetSymbolAddress((void**)&qkv_buf, g_qkv);
    cudaGetSymbolAddress((void**)&att_buf, g_att);

    cudaFuncSetAttribute(attn_kernel,
                         cudaFuncAttributeMaxDynamicSharedMemorySize, ATTN_SMEM);

    // 1) QKV projection: (4096,3072) = X (4096,1024) @ Wqkv^T
    {
        dim3 grid(QKVN / 64, MTOK / 64);
        gemm_abt_kernel<<<grid, 256>>>(x, W_qkv, qkv_buf, MTOK, QKVN, DIM);
    }

    // 2) Causal attention
    {
        dim3 grid(SEQ / 64, BSZ * NH);
        attn_kernel<<<grid, 256, ATTN_SMEM>>>(qkv_buf, att_buf);
    }

    // 3) Output projection: (4096,1024) = att (4096,1024) @ Wout^T
    {
        dim3 grid(DIM / 64, MTOK / 64);
        gemm_abt_kernel<<<grid, 256>>>(att_buf, W_out, out, MTOK, DIM, DIM);
    }
}

// round 3
// speedup vs baseline: 3.9065x; 3.9065x over previous
#include <cuda_runtime.h>
#include <math.h>

#define BSZ   2
#define SEQ   2048
#define DIM   1024
#define NH    16
#define HD    64
#define MTOK  (BSZ * SEQ)       // 4096
#define QKVN  (3 * DIM)         // 3072

// Scratch (no cudaMalloc allowed)
__device__ float g_qkv[(size_t)MTOK * QKVN];  // (4096, 3072) fp32
__device__ float g_att[(size_t)MTOK * DIM];   // (4096, 1024) fp32

// ---------------------------------------------------------------- helpers
__device__ __forceinline__ unsigned f2tf(float x) {
    unsigned r;
    asm("cvt.rna.tf32.f32 %0, %1;" : "=r"(r) : "f"(x));
    return r;
}

__device__ __forceinline__ void mma_tf32(float* c, const unsigned* a,
                                         unsigned b0, unsigned b1) {
    asm volatile(
        "mma.sync.aligned.m16n8k8.row.col.f32.tf32.tf32.f32 "
        "{%0,%1,%2,%3},{%4,%5,%6,%7},{%8,%9},{%0,%1,%2,%3};"
        : "+f"(c[0]), "+f"(c[1]), "+f"(c[2]), "+f"(c[3])
        : "r"(a[0]), "r"(a[1]), "r"(a[2]), "r"(a[3]), "r"(b0), "r"(b1));
}

// ----------------------------------------------------------------------------
// C[M,N] = A[M,K] @ B[N,K]^T  via tf32 mma.  128x128 block, BK=32, 256 thr.
// Warps 2(m) x 4(n): warp tile 64x32 -> 4 m-tiles x 4 n-tiles of m16n8k8.
// ----------------------------------------------------------------------------
#define GPAD 36
__global__ void __launch_bounds__(256, 2)
gemm_tf32_kernel(const float* __restrict__ A, const float* __restrict__ B,
                 float* __restrict__ C, int M, int N, int K) {
    __shared__ unsigned As[128][GPAD];
    __shared__ unsigned Bs[128][GPAD];

    const int tid  = threadIdx.x;
    const int lane = tid & 31;
    const int warp = tid >> 5;
    const int g    = lane >> 2;   // groupID 0..7
    const int tg   = lane & 3;    // threadID_in_group 0..3
    const int wm   = (warp >> 2) * 64;
    const int wn   = (warp & 3) * 32;
    const int m0   = blockIdx.y * 128;
    const int n0   = blockIdx.x * 128;

    float c[4][4][4];
#pragma unroll
    for (int mt = 0; mt < 4; mt++)
#pragma unroll
        for (int nt = 0; nt < 4; nt++)
#pragma unroll
            for (int i = 0; i < 4; i++) c[mt][nt][i] = 0.0f;

    for (int k0 = 0; k0 < K; k0 += 32) {
#pragma unroll
        for (int i = 0; i < 4; i++) {
            int idx = tid + i * 256;
            int r   = idx >> 3;
            int c4  = (idx & 7) * 4;
            float4 va = *(const float4*)&A[(size_t)(m0 + r) * K + k0 + c4];
            float4 vb = *(const float4*)&B[(size_t)(n0 + r) * K + k0 + c4];
            *(uint4*)&As[r][c4] = make_uint4(f2tf(va.x), f2tf(va.y), f2tf(va.z), f2tf(va.w));
            *(uint4*)&Bs[r][c4] = make_uint4(f2tf(vb.x), f2tf(vb.y), f2tf(vb.z), f2tf(vb.w));
        }
        __syncthreads();

#pragma unroll
        for (int k8 = 0; k8 < 4; k8++) {
            unsigned a[4][4], b[4][2];
            const int kc = k8 * 8;
#pragma unroll
            for (int mt = 0; mt < 4; mt++) {
                a[mt][0] = As[wm + mt * 16 + g][kc + tg];
                a[mt][1] = As[wm + mt * 16 + g + 8][kc + tg];
                a[mt][2] = As[wm + mt * 16 + g][kc + tg + 4];
                a[mt][3] = As[wm + mt * 16 + g + 8][kc + tg + 4];
            }
#pragma unroll
            for (int nt = 0; nt < 4; nt++) {
                b[nt][0] = Bs[wn + nt * 8 + g][kc + tg];
                b[nt][1] = Bs[wn + nt * 8 + g][kc + tg + 4];
            }
#pragma unroll
            for (int mt = 0; mt < 4; mt++)
#pragma unroll
                for (int nt = 0; nt < 4; nt++)
                    mma_tf32(c[mt][nt], a[mt], b[nt][0], b[nt][1]);
        }
        __syncthreads();
    }

#pragma unroll
    for (int mt = 0; mt < 4; mt++)
#pragma unroll
        for (int nt = 0; nt < 4; nt++) {
            int row = m0 + wm + mt * 16 + g;
            int col = n0 + wn + nt * 8 + tg * 2;
            *(float2*)&C[(size_t)row * N + col]       = make_float2(c[mt][nt][0], c[mt][nt][1]);
            *(float2*)&C[(size_t)(row + 8) * N + col] = make_float2(c[mt][nt][2], c[mt][nt][3]);
        }
}

// ----------------------------------------------------------------------------
// Flash attention (causal), tf32 mma.  Br=128 q rows per CTA, Bc=64 keys/tile.
// grid (SEQ/128, BSZ*NH), 256 threads = 8 warps, each warp owns 16 q rows.
// ----------------------------------------------------------------------------
#define AST 72      // padded row stride (words) -> conflict-free frag LDS
#define ATTN_SMEM ((128 + 64 + 64 + 128) * AST * 4)

__global__ void __launch_bounds__(256, 1)
attn_tf32_kernel(const float* __restrict__ qkv, float* __restrict__ att) {
    extern __shared__ unsigned smu[];
    unsigned* Qs = smu;                       // [128][AST]
    unsigned* Ks = Qs + 128 * AST;            // [64][AST]
    unsigned* Vs = Ks + 64 * AST;             // [64][AST]
    unsigned* Ps = Vs + 64 * AST;             // [128][AST]

    const int tid  = threadIdx.x;
    const int lane = tid & 31;
    const int warp = tid >> 5;
    const int g    = lane >> 2;
    const int tg   = lane & 3;
    const int bq   = blockIdx.x;
    const int bh   = blockIdx.y;
    const int b    = bh >> 4;
    const int h    = bh & 15;
    const size_t tok0 = (size_t)b * SEQ;
    const int qr   = warp * 16;               // warp's local q-row base

    // Load Q tile (pre-scaled by 1/sqrt(hd) = 0.125)
#pragma unroll
    for (int i = 0; i < 8; i++) {
        int idx = tid + i * 256;
        int r   = idx >> 4;
        int c4  = (idx & 15) * 4;
        float4 v = *(const float4*)&qkv[(tok0 + bq * 128 + r) * QKVN + h * HD + c4];
        *(uint4*)&Qs[r * AST + c4] = make_uint4(f2tf(v.x * 0.125f), f2tf(v.y * 0.125f),
                                                f2tf(v.z * 0.125f), f2tf(v.w * 0.125f));
    }
    __syncthreads();

    // Hoist Q fragments (fixed for the whole kernel)
    unsigned qf[8][4];
#pragma unroll
    for (int k8 = 0; k8 < 8; k8++) {
        int kc = k8 * 8;
        qf[k8][0] = Qs[(qr + g) * AST + kc + tg];
        qf[k8][1] = Qs[(qr + g + 8) * AST + kc + tg];
        qf[k8][2] = Qs[(qr + g) * AST + kc + tg + 4];
        qf[k8][3] = Qs[(qr + g + 8) * AST + kc + tg + 4];
    }

    float oacc[8][4];
#pragma unroll
    for (int n = 0; n < 8; n++)
#pragma unroll
        for (int i = 0; i < 4; i++) oacc[n][i] = 0.0f;
    float mrow[2] = {-INFINITY, -INFINITY};
    float lrow[2] = {0.0f, 0.0f};

    const int r0g = bq * 128 + qr + g;        // global q row (c0/c1)
    const int r1g = r0g + 8;                  // global q row (c2/c3)
    const int ktmax = 2 * bq + 2;

    for (int kt = 0; kt < ktmax; kt++) {
        __syncthreads();   // prev-iter K/V consumers done
#pragma unroll
        for (int i = 0; i < 4; i++) {
            int idx = tid + i * 256;
            int r   = idx >> 4;
            int c4  = (idx & 15) * 4;
            size_t base = (tok0 + kt * 64 + r) * (size_t)QKVN + h * HD + c4;
            float4 vk = *(const float4*)&qkv[base + DIM];
            float4 vv = *(const float4*)&qkv[base + 2 * DIM];
            *(uint4*)&Ks[r * AST + c4] = make_uint4(f2tf(vk.x), f2tf(vk.y), f2tf(vk.z), f2tf(vk.w));
            *(uint4*)&Vs[r * AST + c4] = make_uint4(f2tf(vv.x), f2tf(vv.y), f2tf(vv.z), f2tf(vv.w));
        }
        __syncthreads();

        // S = Q K^T (Q pre-scaled)
        float sacc[8][4];
#pragma unroll
        for (int n = 0; n < 8; n++)
#pragma unroll
            for (int i = 0; i < 4; i++) sacc[n][i] = 0.0f;
#pragma unroll
        for (int k8 = 0; k8 < 8; k8++) {
            int kc = k8 * 8;
#pragma unroll
            for (int n = 0; n < 8; n++) {
                unsigned b0 = Ks[(n * 8 + g) * AST + kc + tg];
                unsigned b1 = Ks[(n * 8 + g) * AST + kc + tg + 4];
                mma_tf32(sacc[n], qf[k8], b0, b1);
            }
        }

        // Causal mask (only the two diagonal tiles can violate)
        if (kt >= 2 * bq) {
#pragma unroll
            for (int n = 0; n < 8; n++) {
#pragma unroll
                for (int ci = 0; ci < 4; ci++) {
                    int col = kt * 64 + n * 8 + tg * 2 + (ci & 1);
                    int rowg = (ci < 2) ? r0g : r1g;
                    if (col > rowg) sacc[n][ci] = -INFINITY;
                }
            }
        }

        // Online softmax (rows live in quads: reduce 16 local + 2 shuffles)
        float mx0 = -INFINITY, mx1 = -INFINITY;
#pragma unroll
        for (int n = 0; n < 8; n++) {
            mx0 = fmaxf(mx0, fmaxf(sacc[n][0], sacc[n][1]));
            mx1 = fmaxf(mx1, fmaxf(sacc[n][2], sacc[n][3]));
        }
#pragma unroll
        for (int off = 1; off <= 2; off <<= 1) {
            mx0 = fmaxf(mx0, __shfl_xor_sync(0xffffffffu, mx0, off));
            mx1 = fmaxf(mx1, __shfl_xor_sync(0xffffffffu, mx1, off));
        }
        float mn0 = fmaxf(mrow[0], mx0);
        float mn1 = fmaxf(mrow[1], mx1);
        float al0 = __expf(mrow[0] - mn0);
        float al1 = __expf(mrow[1] - mn1);

        float rs0 = 0.0f, rs1 = 0.0f;
#pragma unroll
        for (int n = 0; n < 8; n++) {
            sacc[n][0] = __expf(sacc[n][0] - mn0);
            sacc[n][1] = __expf(sacc[n][1] - mn0);
            sacc[n][2] = __expf(sacc[n][2] - mn1);
            sacc[n][3] = __expf(sacc[n][3] - mn1);
            rs0 += sacc[n][0] + sacc[n][1];
            rs1 += sacc[n][2] + sacc[n][3];
        }
#pragma unroll
        for (int off = 1; off <= 2; off <<= 1) {
            rs0 += __shfl_xor_sync(0xffffffffu, rs0, off);
            rs1 += __shfl_xor_sync(0xffffffffu, rs1, off);
        }
        lrow[0] = lrow[0] * al0 + rs0;
        lrow[1] = lrow[1] * al1 + rs1;
        mrow[0] = mn0;
        mrow[1] = mn1;
#pragma unroll
        for (int n = 0; n < 8; n++) {
            oacc[n][0] *= al0; oacc[n][1] *= al0;
            oacc[n][2] *= al1; oacc[n][3] *= al1;
        }

        // Stage P (tf32) in this warp's private smem rows
#pragma unroll
        for (int n = 0; n < 8; n++) {
            *(uint2*)&Ps[(qr + g) * AST + n * 8 + tg * 2] =
                make_uint2(f2tf(sacc[n][0]), f2tf(sacc[n][1]));
            *(uint2*)&Ps[(qr + g + 8) * AST + n * 8 + tg * 2] =
                make_uint2(f2tf(sacc[n][2]), f2tf(sacc[n][3]));
        }
        __syncwarp();

        // O += P @ V
#pragma unroll
        for (int k8 = 0; k8 < 8; k8++) {
            int kc = k8 * 8;
            unsigned pa[4];
            pa[0] = Ps[(qr + g) * AST + kc + tg];
            pa[1] = Ps[(qr + g + 8) * AST + kc + tg];
            pa[2] = Ps[(qr + g) * AST + kc + tg + 4];
            pa[3] = Ps[(qr + g + 8) * AST + kc + tg + 4];
#pragma unroll
            for (int n = 0; n < 8; n++) {
                unsigned b0 = Vs[(kc + tg) * AST + n * 8 + g];
                unsigned b1 = Vs[(kc + tg + 4) * AST + n * 8 + g];
                mma_tf32(oacc[n], pa, b0, b1);
            }
        }
    }

    // Epilogue: normalize, write (B,T,C) layout
    float inv0 = 1.0f / lrow[0];
    float inv1 = 1.0f / lrow[1];
    size_t row0 = tok0 + bq * 128 + qr + g;
#pragma unroll
    for (int n = 0; n < 8; n++) {
        int col = h * HD + n * 8 + tg * 2;
        *(float2*)&att[row0 * DIM + col] =
            make_float2(oacc[n][0] * inv0, oacc[n][1] * inv0);
        *(float2*)&att[(row0 + 8) * DIM + col] =
            make_float2(oacc[n][2] * inv1, oacc[n][3] * inv1);
    }
}

// ----------------------------------------------------------------------------
extern "C" void kernel_launch(void* const* d_in, const int* in_sizes, int n_in,
                              void* d_out, int out_size) {
    const float* x     = (const float*)d_in[0];
    const float* W_qkv = (const float*)d_in[1];
    const float* W_out = (const float*)d_in[2];
    float* out = (float*)d_out;

    float *qkv_buf, *att_buf;
    cudaGetSymbolAddress((void**)&qkv_buf, g_qkv);
    cudaGetSymbolAddress((void**)&att_buf, g_att);

    cudaFuncSetAttribute(attn_tf32_kernel,
                         cudaFuncAttributeMaxDynamicSharedMemorySize, ATTN_SMEM);

    // 1) QKV projection
    {
        dim3 grid(QKVN / 128, MTOK / 128);
        gemm_tf32_kernel<<<grid, 256>>>(x, W_qkv, qkv_buf, MTOK, QKVN, DIM);
    }
    // 2) Causal flash attention
    {
        dim3 grid(SEQ / 128, BSZ * NH);
        attn_tf32_kernel<<<grid, 256, ATTN_SMEM>>>(qkv_buf, att_buf);
    }
    // 3) Output projection
    {
        dim3 grid(DIM / 128, MTOK / 128);
        gemm_tf32_kernel<<<grid, 256>>>(att_buf, W_out, out, MTOK, DIM, DIM);
    }
}

// round 4
// speedup vs baseline: 4.3546x; 1.1147x over previous
#include <cuda_runtime.h>
#include <math.h>

#define BSZ   2
#define SEQ   2048
#define DIM   1024
#define NH    16
#define HD    64
#define MTOK  (BSZ * SEQ)       // 4096
#define QKVN  (3 * DIM)         // 3072

// Scratch (no cudaMalloc allowed)
__device__ float g_qkv[(size_t)MTOK * QKVN];  // (4096, 3072) fp32
__device__ float g_att[(size_t)MTOK * DIM];   // (4096, 1024) fp32

// ---------------------------------------------------------------- helpers
__device__ __forceinline__ unsigned f2tf(float x) {
    unsigned r;
    asm("cvt.rna.tf32.f32 %0, %1;" : "=r"(r) : "f"(x));
    return r;
}

__device__ __forceinline__ void mma_tf32(float* c, const unsigned* a,
                                         unsigned b0, unsigned b1) {
    asm volatile(
        "mma.sync.aligned.m16n8k8.row.col.f32.tf32.tf32.f32 "
        "{%0,%1,%2,%3},{%4,%5,%6,%7},{%8,%9},{%0,%1,%2,%3};"
        : "+f"(c[0]), "+f"(c[1]), "+f"(c[2]), "+f"(c[3])
        : "r"(a[0]), "r"(a[1]), "r"(a[2]), "r"(a[3]), "r"(b0), "r"(b1));
}

__device__ __forceinline__ void cp16(float* smem_dst, const float* gmem_src) {
    unsigned s = (unsigned)__cvta_generic_to_shared(smem_dst);
    asm volatile("cp.async.cg.shared.global [%0], [%1], 16;\n" :: "r"(s), "l"(gmem_src));
}
__device__ __forceinline__ void cp_commit() {
    asm volatile("cp.async.commit_group;\n");
}
template <int N>
__device__ __forceinline__ void cp_wait() {
    asm volatile("cp.async.wait_group %0;\n" :: "n"(N));
}

// ----------------------------------------------------------------------------
// C[M,N] = A[M,K] @ B[N,K]^T  via tf32 mma, 2-stage cp.async pipeline.
// 128x128 block, BK=32, 256 thr. Warps 2(m) x 4(n): warp tile 64x32.
// smem: fp32 staged, cvt.rna at fragment load.
// ----------------------------------------------------------------------------
#define GPAD 36
#define G_STAGE (128 * GPAD)
#define GEMM_SMEM (4 * G_STAGE * 4)   // 2 matrices x 2 stages x 128x36 floats

__global__ void __launch_bounds__(256, 2)
gemm_tf32_kernel(const float* __restrict__ A, const float* __restrict__ B,
                 float* __restrict__ C, int M, int N, int K) {
    extern __shared__ float gsm[];
    float* Asm = gsm;                 // [2][128][GPAD]
    float* Bsm = gsm + 2 * G_STAGE;   // [2][128][GPAD]

    const int tid  = threadIdx.x;
    const int lane = tid & 31;
    const int warp = tid >> 5;
    const int g    = lane >> 2;
    const int tg   = lane & 3;
    const int wm   = (warp >> 2) * 64;
    const int wn   = (warp & 3) * 32;
    const int m0   = blockIdx.y * 128;
    const int n0   = blockIdx.x * 128;

    const int ldr = tid >> 3;          // 0..31? no: tid/8 -> 0..31  (row per 8 threads)
    const int ldc = (tid & 7) * 4;     // 0..28

    float c[4][4][4];
#pragma unroll
    for (int mt = 0; mt < 4; mt++)
#pragma unroll
        for (int nt = 0; nt < 4; nt++)
#pragma unroll
            for (int i = 0; i < 4; i++) c[mt][nt][i] = 0.0f;

    const int nIter = K >> 5;          // K/32

    // prologue: stage 0
#pragma unroll
    for (int i = 0; i < 4; i++) {
        int r = ldr + i * 32;
        cp16(&Asm[r * GPAD + ldc], &A[(size_t)(m0 + r) * K + ldc]);
        cp16(&Bsm[r * GPAD + ldc], &B[(size_t)(n0 + r) * K + ldc]);
    }
    cp_commit();

#pragma unroll 1
    for (int it = 0; it < nIter; it++) {
        const int cur = it & 1;
        if (it + 1 < nIter) {
            const int nxt = cur ^ 1;
            const int k0 = (it + 1) << 5;
#pragma unroll
            for (int i = 0; i < 4; i++) {
                int r = ldr + i * 32;
                cp16(&Asm[nxt * G_STAGE + r * GPAD + ldc], &A[(size_t)(m0 + r) * K + k0 + ldc]);
                cp16(&Bsm[nxt * G_STAGE + r * GPAD + ldc], &B[(size_t)(n0 + r) * K + k0 + ldc]);
            }
            cp_commit();
            cp_wait<1>();
        } else {
            cp_wait<0>();
        }
        __syncthreads();

        const float* As = Asm + cur * G_STAGE;
        const float* Bs = Bsm + cur * G_STAGE;
#pragma unroll
        for (int k8 = 0; k8 < 4; k8++) {
            const int kc = k8 * 8;
            unsigned a[4][4], b[4][2];
#pragma unroll
            for (int mt = 0; mt < 4; mt++) {
                a[mt][0] = f2tf(As[(wm + mt * 16 + g) * GPAD + kc + tg]);
                a[mt][1] = f2tf(As[(wm + mt * 16 + g + 8) * GPAD + kc + tg]);
                a[mt][2] = f2tf(As[(wm + mt * 16 + g) * GPAD + kc + tg + 4]);
                a[mt][3] = f2tf(As[(wm + mt * 16 + g + 8) * GPAD + kc + tg + 4]);
            }
#pragma unroll
            for (int nt = 0; nt < 4; nt++) {
                b[nt][0] = f2tf(Bs[(wn + nt * 8 + g) * GPAD + kc + tg]);
                b[nt][1] = f2tf(Bs[(wn + nt * 8 + g) * GPAD + kc + tg + 4]);
            }
#pragma unroll
            for (int mt = 0; mt < 4; mt++)
#pragma unroll
                for (int nt = 0; nt < 4; nt++)
                    mma_tf32(c[mt][nt], a[mt], b[nt][0], b[nt][1]);
        }
        __syncthreads();
    }

#pragma unroll
    for (int mt = 0; mt < 4; mt++)
#pragma unroll
        for (int nt = 0; nt < 4; nt++) {
            int row = m0 + wm + mt * 16 + g;
            int col = n0 + wn + nt * 8 + tg * 2;
            *(float2*)&C[(size_t)row * N + col]       = make_float2(c[mt][nt][0], c[mt][nt][1]);
            *(float2*)&C[(size_t)(row + 8) * N + col] = make_float2(c[mt][nt][2], c[mt][nt][3]);
        }
}

// ----------------------------------------------------------------------------
// Flash attention (causal), tf32 mma, 2-stage cp.async K/V pipeline.
// Br=128 q rows per CTA, Bc=64 keys per tile. grid (SEQ/128, BSZ*NH), 256 thr.
// smem: QP [128][68] (P overlays dead Q), K [2][64][68], V [2][64][72].
// ----------------------------------------------------------------------------
#define QP_PAD 68
#define K_PAD  68
#define V_PAD  72
#define K_STAGE (64 * K_PAD)
#define V_STAGE (64 * V_PAD)
#define ATTN_SMEM ((128 * QP_PAD + 2 * K_STAGE + 2 * V_STAGE) * 4)

__device__ __forceinline__ void attn_prefetch(float* Ks, float* Vs,
                                              const float* __restrict__ qkv,
                                              size_t tok0, int h, int kt,
                                              int stage, int tid) {
#pragma unroll
    for (int i = 0; i < 4; i++) {
        int idx = tid + i * 256;
        int r   = idx >> 4;
        int c4  = (idx & 15) * 4;
        const float* base = &qkv[(tok0 + kt * 64 + r) * (size_t)QKVN + h * HD + c4];
        cp16(&Ks[stage * K_STAGE + r * K_PAD + c4], base + DIM);
        cp16(&Vs[stage * V_STAGE + r * V_PAD + c4], base + 2 * DIM);
    }
    cp_commit();
}

__global__ void __launch_bounds__(256, 1)
attn_tf32_kernel(const float* __restrict__ qkv, float* __restrict__ att) {
    extern __shared__ float smf[];
    float* Qs = smf;                          // [128][QP_PAD]; reused as Ps
    float* Ks = smf + 128 * QP_PAD;           // [2][64][K_PAD]
    float* Vs = Ks + 2 * K_STAGE;             // [2][64][V_PAD]

    const int tid  = threadIdx.x;
    const int lane = tid & 31;
    const int warp = tid >> 5;
    const int g    = lane >> 2;
    const int tg   = lane & 3;
    const int bq   = blockIdx.x;
    const int bh   = blockIdx.y;
    const int b    = bh >> 4;
    const int h    = bh & 15;
    const size_t tok0 = (size_t)b * SEQ;
    const int qr   = warp * 16;

    const int ktmax = 2 * bq + 2;

    // Kick off K/V stage 0 immediately
    attn_prefetch(Ks, Vs, qkv, tok0, h, 0, 0, tid);

    // Load Q tile (pre-scaled by 0.125, rna-rounded to tf32)
#pragma unroll
    for (int i = 0; i < 8; i++) {
        int idx = tid + i * 256;
        int r   = idx >> 4;
        int c4  = (idx & 15) * 4;
        float4 v = *(const float4*)&qkv[(tok0 + bq * 128 + r) * QKVN + h * HD + c4];
        Qs[r * QP_PAD + c4 + 0] = __uint_as_float(f2tf(v.x * 0.125f));
        Qs[r * QP_PAD + c4 + 1] = __uint_as_float(f2tf(v.y * 0.125f));
        Qs[r * QP_PAD + c4 + 2] = __uint_as_float(f2tf(v.z * 0.125f));
        Qs[r * QP_PAD + c4 + 3] = __uint_as_float(f2tf(v.w * 0.125f));
    }
    __syncthreads();

    // Hoist Q fragments (warp reads only its own 16 rows)
    unsigned qf[8][4];
    {
        const unsigned* Qu = (const unsigned*)Qs;
#pragma unroll
        for (int k8 = 0; k8 < 8; k8++) {
            int kc = k8 * 8;
            qf[k8][0] = Qu[(qr + g) * QP_PAD + kc + tg];
            qf[k8][1] = Qu[(qr + g + 8) * QP_PAD + kc + tg];
            qf[k8][2] = Qu[(qr + g) * QP_PAD + kc + tg + 4];
            qf[k8][3] = Qu[(qr + g + 8) * QP_PAD + kc + tg + 4];
        }
    }
    __syncthreads();   // everyone hoisted before Qs is reused as Ps

    unsigned* Ps = (unsigned*)Qs;   // overlay; each warp touches only its rows

    float oacc[8][4];
#pragma unroll
    for (int n = 0; n < 8; n++)
#pragma unroll
        for (int i = 0; i < 4; i++) oacc[n][i] = 0.0f;
    float mrow[2] = {-INFINITY, -INFINITY};
    float lrow[2] = {0.0f, 0.0f};

    const int r0g = bq * 128 + qr + g;
    const int r1g = r0g + 8;

#pragma unroll 1
    for (int kt = 0; kt < ktmax; kt++) {
        if (kt + 1 < ktmax) {
            attn_prefetch(Ks, Vs, qkv, tok0, h, kt + 1, (kt + 1) & 1, tid);
            cp_wait<1>();
        } else {
            cp_wait<0>();
        }
        __syncthreads();

        const float* Kst = Ks + (kt & 1) * K_STAGE;
        const float* Vst = Vs + (kt & 1) * V_STAGE;

        // S = Q K^T
        float sacc[8][4];
#pragma unroll
        for (int n = 0; n < 8; n++)
#pragma unroll
            for (int i = 0; i < 4; i++) sacc[n][i] = 0.0f;
#pragma unroll
        for (int k8 = 0; k8 < 8; k8++) {
            int kc = k8 * 8;
#pragma unroll
            for (int n = 0; n < 8; n++) {
                unsigned b0 = f2tf(Kst[(n * 8 + g) * K_PAD + kc + tg]);
                unsigned b1 = f2tf(Kst[(n * 8 + g) * K_PAD + kc + tg + 4]);
                mma_tf32(sacc[n], qf[k8], b0, b1);
            }
        }

        // Causal mask (only last two key-tiles can violate)
        if (kt >= 2 * bq) {
#pragma unroll
            for (int n = 0; n < 8; n++) {
#pragma unroll
                for (int ci = 0; ci < 4; ci++) {
                    int col = kt * 64 + n * 8 + tg * 2 + (ci & 1);
                    int rowg = (ci < 2) ? r0g : r1g;
                    if (col > rowg) sacc[n][ci] = -INFINITY;
                }
            }
        }

        // Online softmax (quad-local rows; 2 shuffles per reduce)
        float mx0 = -INFINITY, mx1 = -INFINITY;
#pragma unroll
        for (int n = 0; n < 8; n++) {
            mx0 = fmaxf(mx0, fmaxf(sacc[n][0], sacc[n][1]));
            mx1 = fmaxf(mx1, fmaxf(sacc[n][2], sacc[n][3]));
        }
#pragma unroll
        for (int off = 1; off <= 2; off <<= 1) {
            mx0 = fmaxf(mx0, __shfl_xor_sync(0xffffffffu, mx0, off));
            mx1 = fmaxf(mx1, __shfl_xor_sync(0xffffffffu, mx1, off));
        }
        float mn0 = fmaxf(mrow[0], mx0);
        float mn1 = fmaxf(mrow[1], mx1);
        float al0 = __expf(mrow[0] - mn0);
        float al1 = __expf(mrow[1] - mn1);

        float rs0 = 0.0f, rs1 = 0.0f;
#pragma unroll
        for (int n = 0; n < 8; n++) {
            sacc[n][0] = __expf(sacc[n][0] - mn0);
            sacc[n][1] = __expf(sacc[n][1] - mn0);
            sacc[n][2] = __expf(sacc[n][2] - mn1);
            sacc[n][3] = __expf(sacc[n][3] - mn1);
            rs0 += sacc[n][0] + sacc[n][1];
            rs1 += sacc[n][2] + sacc[n][3];
        }
#pragma unroll
        for (int off = 1; off <= 2; off <<= 1) {
            rs0 += __shfl_xor_sync(0xffffffffu, rs0, off);
            rs1 += __shfl_xor_sync(0xffffffffu, rs1, off);
        }
        lrow[0] = lrow[0] * al0 + rs0;
        lrow[1] = lrow[1] * al1 + rs1;
        mrow[0] = mn0;
        mrow[1] = mn1;
#pragma unroll
        for (int n = 0; n < 8; n++) {
            oacc[n][0] *= al0; oacc[n][1] *= al0;
            oacc[n][2] *= al1; oacc[n][3] *= al1;
        }

        // Stage P (tf32 bits) in warp-private smem rows
#pragma unroll
        for (int n = 0; n < 8; n++) {
            *(uint2*)&Ps[(qr + g) * QP_PAD + n * 8 + tg * 2] =
                make_uint2(f2tf(sacc[n][0]), f2tf(sacc[n][1]));
            *(uint2*)&Ps[(qr + g + 8) * QP_PAD + n * 8 + tg * 2] =
                make_uint2(f2tf(sacc[n][2]), f2tf(sacc[n][3]));
        }
        __syncwarp();

        // O += P @ V
#pragma unroll
        for (int k8 = 0; k8 < 8; k8++) {
            int kc = k8 * 8;
            unsigned pa[4];
            pa[0] = Ps[(qr + g) * QP_PAD + kc + tg];
            pa[1] = Ps[(qr + g + 8) * QP_PAD + kc + tg];
            pa[2] = Ps[(qr + g) * QP_PAD + kc + tg + 4];
            pa[3] = Ps[(qr + g + 8) * QP_PAD + kc + tg + 4];
#pragma unroll
            for (int n = 0; n < 8; n++) {
                unsigned b0 = f2tf(Vst[(kc + tg) * V_PAD + n * 8 + g]);
                unsigned b1 = f2tf(Vst[(kc + tg + 4) * V_PAD + n * 8 + g]);
                mma_tf32(oacc[n], pa, b0, b1);
            }
        }
        __syncthreads();   // all warps done with this stage before kt+2 prefetch lands
    }

    // Epilogue
    float inv0 = 1.0f / lrow[0];
    float inv1 = 1.0f / lrow[1];
    size_t row0 = tok0 + bq * 128 + qr + g;
#pragma unroll
    for (int n = 0; n < 8; n++) {
        int col = h * HD + n * 8 + tg * 2;
        *(float2*)&att[row0 * DIM + col] =
            make_float2(oacc[n][0] * inv0, oacc[n][1] * inv0);
        *(float2*)&att[(row0 + 8) * DIM + col] =
            make_float2(oacc[n][2] * inv1, oacc[n][3] * inv1);
    }
}

// ----------------------------------------------------------------------------
extern "C" void kernel_launch(void* const* d_in, const int* in_sizes, int n_in,
                              void* d_out, int out_size) {
    const float* x     = (const float*)d_in[0];
    const float* W_qkv = (const float*)d_in[1];
    const float* W_out = (const float*)d_in[2];
    float* out = (float*)d_out;

    float *qkv_buf, *att_buf;
    cudaGetSymbolAddress((void**)&qkv_buf, g_qkv);
    cudaGetSymbolAddress((void**)&att_buf, g_att);

    static int configured = 0;
    // cudaFuncSetAttribute is capture-safe (host-side), call every time (deterministic)
    cudaFuncSetAttribute(gemm_tf32_kernel,
                         cudaFuncAttributeMaxDynamicSharedMemorySize, GEMM_SMEM);
    cudaFuncSetAttribute(attn_tf32_kernel,
                         cudaFuncAttributeMaxDynamicSharedMemorySize, ATTN_SMEM);
    (void)configured;

    // 1) QKV projection
    {
        dim3 grid(QKVN / 128, MTOK / 128);
        gemm_tf32_kernel<<<grid, 256, GEMM_SMEM>>>(x, W_qkv, qkv_buf, MTOK, QKVN, DIM);
    }
    // 2) Causal flash attention
    {
        dim3 grid(SEQ / 128, BSZ * NH);
        attn_tf32_kernel<<<grid, 256, ATTN_SMEM>>>(qkv_buf, att_buf);
    }
    // 3) Output projection
    {
        dim3 grid(DIM / 128, MTOK / 128);
        gemm_tf32_kernel<<<grid, 256, GEMM_SMEM>>>(att_buf, W_out, out, MTOK, DIM, DIM);
    }
}

// round 6
// speedup vs baseline: 4.5687x; 1.0492x over previous
#include <cuda_runtime.h>
#include <math.h>
#include <stdint.h>

#define BSZ   2
#define SEQ   2048
#define DIM   1024
#define NH    16
#define HD    64
#define MTOK  (BSZ * SEQ)       // 4096
#define QKVN  (3 * DIM)         // 3072

// Scratch (no cudaMalloc allowed)
__device__ float g_qkv[(size_t)MTOK * QKVN];   // (4096, 3072) rna-tf32 values
__device__ float g_att[(size_t)MTOK * DIM];    // (4096, 1024) rna-tf32 values
__device__ float g_xr [(size_t)MTOK * DIM];    // x rounded
__device__ float g_wqr[(size_t)QKVN * DIM];    // W_qkv rounded
__device__ float g_wor[(size_t)DIM  * DIM];    // W_out rounded

// ---------------------------------------------------------------- helpers
__device__ __forceinline__ unsigned f2tf(float x) {
    unsigned r;
    asm("cvt.rna.tf32.f32 %0, %1;" : "=r"(r) : "f"(x));
    return r;
}

__device__ __forceinline__ void mma_tf32(float* c, const unsigned* a,
                                         unsigned b0, unsigned b1) {
    asm volatile(
        "mma.sync.aligned.m16n8k8.row.col.f32.tf32.tf32.f32 "
        "{%0,%1,%2,%3},{%4,%5,%6,%7},{%8,%9},{%0,%1,%2,%3};"
        : "+f"(c[0]), "+f"(c[1]), "+f"(c[2]), "+f"(c[3])
        : "r"(a[0]), "r"(a[1]), "r"(a[2]), "r"(a[3]), "r"(b0), "r"(b1));
}

__device__ __forceinline__ void cp16(void* smem_dst, const void* gmem_src) {
    unsigned s = (unsigned)__cvta_generic_to_shared(smem_dst);
    asm volatile("cp.async.cg.shared.global [%0], [%1], 16;\n" :: "r"(s), "l"(gmem_src));
}
__device__ __forceinline__ void cp_commit() {
    asm volatile("cp.async.commit_group;\n");
}
template <int N>
__device__ __forceinline__ void cp_wait() {
    asm volatile("cp.async.wait_group %0;\n" :: "n"(N));
}

// ----------------------------------------------------------------------------
// Pre-pass: round fp32 -> rna-tf32 (value stays fp32-representable)
// ----------------------------------------------------------------------------
__global__ void round_tf32_kernel(const float* __restrict__ in,
                                  float* __restrict__ out, int n4) {
    int i = blockIdx.x * blockDim.x + threadIdx.x;
    if (i < n4) {
        float4 v = ((const float4*)in)[i];
        float4 o;
        o.x = __uint_as_float(f2tf(v.x));
        o.y = __uint_as_float(f2tf(v.y));
        o.z = __uint_as_float(f2tf(v.z));
        o.w = __uint_as_float(f2tf(v.w));
        ((float4*)out)[i] = o;
    }
}

// ----------------------------------------------------------------------------
// C[M,N] = A[M,K] @ B[N,K]^T  via tf32 mma, 2-stage cp.async pipeline.
// Inputs MUST be pre-rounded tf32 values (no cvt in mainloop).
// 128x128 block, BK=32, 256 thr. Warps 2(m) x 4(n): warp tile 64x32.
// ROUND: round output to rna-tf32 on store (for buffers consumed by tf32 mma).
// ----------------------------------------------------------------------------
#define GPAD 36
#define G_STAGE (128 * GPAD)
#define GEMM_SMEM (4 * G_STAGE * 4)

template <bool ROUND>
__global__ void __launch_bounds__(256, 2)
gemm_tf32_kernel(const float* __restrict__ A, const float* __restrict__ B,
                 float* __restrict__ C, int M, int N, int K) {
    extern __shared__ float gsm[];
    float* Asm = gsm;                 // [2][128][GPAD]
    float* Bsm = gsm + 2 * G_STAGE;   // [2][128][GPAD]

    const int tid  = threadIdx.x;
    const int lane = tid & 31;
    const int warp = tid >> 5;
    const int g    = lane >> 2;
    const int tg   = lane & 3;
    const int wm   = (warp >> 2) * 64;
    const int wn   = (warp & 3) * 32;
    const int m0   = blockIdx.y * 128;
    const int n0   = blockIdx.x * 128;

    const int ldr = tid >> 3;          // 0..31 (row group)
    const int ldc = (tid & 7) * 4;     // 0..28

    float c[4][4][4];
#pragma unroll
    for (int mt = 0; mt < 4; mt++)
#pragma unroll
        for (int nt = 0; nt < 4; nt++)
#pragma unroll
            for (int i = 0; i < 4; i++) c[mt][nt][i] = 0.0f;

    const int nIter = K >> 5;

    // prologue: stage 0
#pragma unroll
    for (int i = 0; i < 4; i++) {
        int r = ldr + i * 32;
        cp16(&Asm[r * GPAD + ldc], &A[(size_t)(m0 + r) * K + ldc]);
        cp16(&Bsm[r * GPAD + ldc], &B[(size_t)(n0 + r) * K + ldc]);
    }
    cp_commit();

#pragma unroll 1
    for (int it = 0; it < nIter; it++) {
        const int cur = it & 1;
        if (it + 1 < nIter) {
            const int nxt = cur ^ 1;
            const int k0 = (it + 1) << 5;
#pragma unroll
            for (int i = 0; i < 4; i++) {
                int r = ldr + i * 32;
                cp16(&Asm[nxt * G_STAGE + r * GPAD + ldc], &A[(size_t)(m0 + r) * K + k0 + ldc]);
                cp16(&Bsm[nxt * G_STAGE + r * GPAD + ldc], &B[(size_t)(n0 + r) * K + k0 + ldc]);
            }
            cp_commit();
            cp_wait<1>();
        } else {
            cp_wait<0>();
        }
        __syncthreads();

        const unsigned* As = (const unsigned*)(Asm + cur * G_STAGE);
        const unsigned* Bs = (const unsigned*)(Bsm + cur * G_STAGE);
#pragma unroll
        for (int k8 = 0; k8 < 4; k8++) {
            const int kc = k8 * 8;
            unsigned a[4][4], b[4][2];
#pragma unroll
            for (int mt = 0; mt < 4; mt++) {
                a[mt][0] = As[(wm + mt * 16 + g) * GPAD + kc + tg];
                a[mt][1] = As[(wm + mt * 16 + g + 8) * GPAD + kc + tg];
                a[mt][2] = As[(wm + mt * 16 + g) * GPAD + kc + tg + 4];
                a[mt][3] = As[(wm + mt * 16 + g + 8) * GPAD + kc + tg + 4];
            }
#pragma unroll
            for (int nt = 0; nt < 4; nt++) {
                b[nt][0] = Bs[(wn + nt * 8 + g) * GPAD + kc + tg];
                b[nt][1] = Bs[(wn + nt * 8 + g) * GPAD + kc + tg + 4];
            }
#pragma unroll
            for (int mt = 0; mt < 4; mt++)
#pragma unroll
                for (int nt = 0; nt < 4; nt++)
                    mma_tf32(c[mt][nt], a[mt], b[nt][0], b[nt][1]);
        }
        __syncthreads();
    }

#pragma unroll
    for (int mt = 0; mt < 4; mt++)
#pragma unroll
        for (int nt = 0; nt < 4; nt++) {
            int row = m0 + wm + mt * 16 + g;
            int col = n0 + wn + nt * 8 + tg * 2;
            float v0 = c[mt][nt][0], v1 = c[mt][nt][1];
            float v2 = c[mt][nt][2], v3 = c[mt][nt][3];
            if (ROUND) {
                v0 = __uint_as_float(f2tf(v0));
                v1 = __uint_as_float(f2tf(v1));
                v2 = __uint_as_float(f2tf(v2));
                v3 = __uint_as_float(f2tf(v3));
            }
            *(float2*)&C[(size_t)row * N + col]       = make_float2(v0, v1);
            *(float2*)&C[(size_t)(row + 8) * N + col] = make_float2(v2, v3);
        }
}

// ----------------------------------------------------------------------------
// Flash attention (causal), tf32 mma, 2-stage cp.async K/V pipeline.
// qkv is pre-rounded tf32 values -> NO cvt on Q/K/V paths; only P (exp output)
// is rounded. Largest-bq CTAs launch first for wave balance.
// ----------------------------------------------------------------------------
#define QP_PAD 68
#define K_PAD  68
#define V_PAD  72
#define K_STAGE (64 * K_PAD)
#define V_STAGE (64 * V_PAD)
#define ATTN_SMEM ((128 * QP_PAD + 2 * K_STAGE + 2 * V_STAGE) * 4)

__device__ __forceinline__ void attn_prefetch(float* Ks, float* Vs,
                                              const float* __restrict__ qkv,
                                              size_t tok0, int h, int kt,
                                              int stage, int tid) {
#pragma unroll
    for (int i = 0; i < 4; i++) {
        int idx = tid + i * 256;
        int r   = idx >> 4;
        int c4  = (idx & 15) * 4;
        const float* base = &qkv[(tok0 + kt * 64 + r) * (size_t)QKVN + h * HD + c4];
        cp16(&Ks[stage * K_STAGE + r * K_PAD + c4], base + DIM);
        cp16(&Vs[stage * V_STAGE + r * V_PAD + c4], base + 2 * DIM);
    }
    cp_commit();
}

__global__ void __launch_bounds__(256, 1)
attn_tf32_kernel(const float* __restrict__ qkv, float* __restrict__ att) {
    extern __shared__ float smf[];
    float* Qs = smf;                          // [128][QP_PAD]; reused as Ps
    float* Ks = smf + 128 * QP_PAD;           // [2][64][K_PAD]
    float* Vs = Ks + 2 * K_STAGE;             // [2][64][V_PAD]

    const int tid  = threadIdx.x;
    const int lane = tid & 31;
    const int warp = tid >> 5;
    const int g    = lane >> 2;
    const int tg   = lane & 3;
    const int bq   = gridDim.x - 1 - blockIdx.x;   // largest tiles first
    const int bh   = blockIdx.y;
    const int b    = bh >> 4;
    const int h    = bh & 15;
    const size_t tok0 = (size_t)b * SEQ;
    const int qr   = warp * 16;

    const int ktmax = 2 * bq + 2;

    attn_prefetch(Ks, Vs, qkv, tok0, h, 0, 0, tid);

    // Q: pre-rounded; *0.125 (power of 2) is exact and stays tf32-valued
#pragma unroll
    for (int i = 0; i < 8; i++) {
        int idx = tid + i * 256;
        int r   = idx >> 4;
        int c4  = (idx & 15) * 4;
        float4 v = *(const float4*)&qkv[(tok0 + bq * 128 + r) * QKVN + h * HD + c4];
        Qs[r * QP_PAD + c4 + 0] = v.x * 0.125f;
        Qs[r * QP_PAD + c4 + 1] = v.y * 0.125f;
        Qs[r * QP_PAD + c4 + 2] = v.z * 0.125f;
        Qs[r * QP_PAD + c4 + 3] = v.w * 0.125f;
    }
    __syncthreads();

    unsigned qf[8][4];
    {
        const unsigned* Qu = (const unsigned*)Qs;
#pragma unroll
        for (int k8 = 0; k8 < 8; k8++) {
            int kc = k8 * 8;
            qf[k8][0] = Qu[(qr + g) * QP_PAD + kc + tg];
            qf[k8][1] = Qu[(qr + g + 8) * QP_PAD + kc + tg];
            qf[k8][2] = Qu[(qr + g) * QP_PAD + kc + tg + 4];
            qf[k8][3] = Qu[(qr + g + 8) * QP_PAD + kc + tg + 4];
        }
    }
    __syncthreads();

    unsigned* Ps = (unsigned*)Qs;

    float oacc[8][4];
#pragma unroll
    for (int n = 0; n < 8; n++)
#pragma unroll
        for (int i = 0; i < 4; i++) oacc[n][i] = 0.0f;
    float mrow[2] = {-INFINITY, -INFINITY};
    float lrow[2] = {0.0f, 0.0f};

    const int r0g = bq * 128 + qr + g;
    const int r1g = r0g + 8;

#pragma unroll 1
    for (int kt = 0; kt < ktmax; kt++) {
        if (kt + 1 < ktmax) {
            attn_prefetch(Ks, Vs, qkv, tok0, h, kt + 1, (kt + 1) & 1, tid);
            cp_wait<1>();
        } else {
            cp_wait<0>();
        }
        __syncthreads();

        const unsigned* Kst = (const unsigned*)(Ks + (kt & 1) * K_STAGE);
        const unsigned* Vst = (const unsigned*)(Vs + (kt & 1) * V_STAGE);

        float sacc[8][4];
#pragma unroll
        for (int n = 0; n < 8; n++)
#pragma unroll
            for (int i = 0; i < 4; i++) sacc[n][i] = 0.0f;
#pragma unroll
        for (int k8 = 0; k8 < 8; k8++) {
            int kc = k8 * 8;
#pragma unroll
            for (int n = 0; n < 8; n++) {
                unsigned b0 = Kst[(n * 8 + g) * K_PAD + kc + tg];
                unsigned b1 = Kst[(n * 8 + g) * K_PAD + kc + tg + 4];
                mma_tf32(sacc[n], qf[k8], b0, b1);
            }
        }

        if (kt >= 2 * bq) {
#pragma unroll
            for (int n = 0; n < 8; n++) {
#pragma unroll
                for (int ci = 0; ci < 4; ci++) {
                    int col = kt * 64 + n * 8 + tg * 2 + (ci & 1);
                    int rowg = (ci < 2) ? r0g : r1g;
                    if (col > rowg) sacc[n][ci] = -INFINITY;
                }
            }
        }

        float mx0 = -INFINITY, mx1 = -INFINITY;
#pragma unroll
        for (int n = 0; n < 8; n++) {
            mx0 = fmaxf(mx0, fmaxf(sacc[n][0], sacc[n][1]));
            mx1 = fmaxf(mx1, fmaxf(sacc[n][2], sacc[n][3]));
        }
#pragma unroll
        for (int off = 1; off <= 2; off <<= 1) {
            mx0 = fmaxf(mx0, __shfl_xor_sync(0xffffffffu, mx0, off));
            mx1 = fmaxf(mx1, __shfl_xor_sync(0xffffffffu, mx1, off));
        }
        float mn0 = fmaxf(mrow[0], mx0);
        float mn1 = fmaxf(mrow[1], mx1);
        float al0 = __expf(mrow[0] - mn0);
        float al1 = __expf(mrow[1] - mn1);

        float rs0 = 0.0f, rs1 = 0.0f;
#pragma unroll
        for (int n = 0; n < 8; n++) {
            sacc[n][0] = __expf(sacc[n][0] - mn0);
            sacc[n][1] = __expf(sacc[n][1] - mn0);
            sacc[n][2] = __expf(sacc[n][2] - mn1);
            sacc[n][3] = __expf(sacc[n][3] - mn1);
            rs0 += sacc[n][0] + sacc[n][1];
            rs1 += sacc[n][2] + sacc[n][3];
        }
#pragma unroll
        for (int off = 1; off <= 2; off <<= 1) {
            rs0 += __shfl_xor_sync(0xffffffffu, rs0, off);
            rs1 += __shfl_xor_sync(0xffffffffu, rs1, off);
        }
        lrow[0] = lrow[0] * al0 + rs0;
        lrow[1] = lrow[1] * al1 + rs1;
        mrow[0] = mn0;
        mrow[1] = mn1;
#pragma unroll
        for (int n = 0; n < 8; n++) {
            oacc[n][0] *= al0; oacc[n][1] *= al0;
            oacc[n][2] *= al1; oacc[n][3] *= al1;
        }

#pragma unroll
        for (int n = 0; n < 8; n++) {
            *(uint2*)&Ps[(qr + g) * QP_PAD + n * 8 + tg * 2] =
                make_uint2(f2tf(sacc[n][0]), f2tf(sacc[n][1]));
            *(uint2*)&Ps[(qr + g + 8) * QP_PAD + n * 8 + tg * 2] =
                make_uint2(f2tf(sacc[n][2]), f2tf(sacc[n][3]));
        }
        __syncwarp();

#pragma unroll
        for (int k8 = 0; k8 < 8; k8++) {
            int kc = k8 * 8;
            unsigned pa[4];
            pa[0] = Ps[(qr + g) * QP_PAD + kc + tg];
            pa[1] = Ps[(qr + g + 8) * QP_PAD + kc + tg];
            pa[2] = Ps[(qr + g) * QP_PAD + kc + tg + 4];
            pa[3] = Ps[(qr + g + 8) * QP_PAD + kc + tg + 4];
#pragma unroll
            for (int n = 0; n < 8; n++) {
                unsigned b0 = Vst[(kc + tg) * V_PAD + n * 8 + g];
                unsigned b1 = Vst[(kc + tg + 4) * V_PAD + n * 8 + g];
                mma_tf32(oacc[n], pa, b0, b1);
            }
        }
        __syncthreads();
    }

    // Epilogue: write rna-tf32-rounded values (GEMM2 consumes without cvt)
    float inv0 = 1.0f / lrow[0];
    float inv1 = 1.0f / lrow[1];
    size_t row0 = tok0 + bq * 128 + qr + g;
#pragma unroll
    for (int n = 0; n < 8; n++) {
        int col = h * HD + n * 8 + tg * 2;
        *(float2*)&att[row0 * DIM + col] =
            make_float2(__uint_as_float(f2tf(oacc[n][0] * inv0)),
                        __uint_as_float(f2tf(oacc[n][1] * inv0)));
        *(float2*)&att[(row0 + 8) * DIM + col] =
            make_float2(__uint_as_float(f2tf(oacc[n][2] * inv1)),
                        __uint_as_float(f2tf(oacc[n][3] * inv1)));
    }
}

// ----------------------------------------------------------------------------
extern "C" void kernel_launch(void* const* d_in, const int* in_sizes, int n_in,
                              void* d_out, int out_size) {
    const float* x     = (const float*)d_in[0];
    const float* W_qkv = (const float*)d_in[1];
    const float* W_out = (const float*)d_in[2];
    float* out = (float*)d_out;

    float *qkv_buf, *att_buf, *xr, *wqr, *wor;
    cudaGetSymbolAddress((void**)&qkv_buf, g_qkv);
    cudaGetSymbolAddress((void**)&att_buf, g_att);
    cudaGetSymbolAddress((void**)&xr,  g_xr);
    cudaGetSymbolAddress((void**)&wqr, g_wqr);
    cudaGetSymbolAddress((void**)&wor, g_wor);

    cudaFuncSetAttribute(gemm_tf32_kernel<true>,
                         cudaFuncAttributeMaxDynamicSharedMemorySize, GEMM_SMEM);
    cudaFuncSetAttribute(gemm_tf32_kernel<false>,
                         cudaFuncAttributeMaxDynamicSharedMemorySize, GEMM_SMEM);
    cudaFuncSetAttribute(attn_tf32_kernel,
                         cudaFuncAttributeMaxDynamicSharedMemorySize, ATTN_SMEM);

    // 0) One-time rounding pre-pass (~8 us)
    {
        int n4x = MTOK * DIM / 4;
        round_tf32_kernel<<<(n4x + 255) / 256, 256>>>(x, xr, n4x);
        int n4q = QKVN * DIM / 4;
        round_tf32_kernel<<<(n4q + 255) / 256, 256>>>(W_qkv, wqr, n4q);
        int n4o = DIM * DIM / 4;
        round_tf32_kernel<<<(n4o + 255) / 256, 256>>>(W_out, wor, n4o);
    }

    // 1) QKV projection (rounded output -> attention consumes without cvt)
    {
        dim3 grid(QKVN / 128, MTOK / 128);
        gemm_tf32_kernel<true><<<grid, 256, GEMM_SMEM>>>(xr, wqr, qkv_buf, MTOK, QKVN, DIM);
    }
    // 2) Causal flash attention (rounded output)
    {
        dim3 grid(SEQ / 128, BSZ * NH);
        attn_tf32_kernel<<<grid, 256, ATTN_SMEM>>>(qkv_buf, att_buf);
    }
    // 3) Output projection (raw fp32 output)
    {
        dim3 grid(DIM / 128, MTOK / 128);
        gemm_tf32_kernel<false><<<grid, 256, GEMM_SMEM>>>(att_buf, wor, out, MTOK, DIM, DIM);
    }
}

// round 8
// speedup vs baseline: 4.9710x; 1.0880x over previous
#include <cuda_runtime.h>
#include <math.h>
#include <stdint.h>

#define BSZ   2
#define SEQ   2048
#define DIM   1024
#define NH    16
#define HD    64
#define MTOK  (BSZ * SEQ)       // 4096
#define QKVN  (3 * DIM)         // 3072

// Scratch (no cudaMalloc allowed)
__device__ float g_qkv[(size_t)MTOK * QKVN];   // rna-tf32 values
__device__ float g_att[(size_t)MTOK * DIM];    // rna-tf32 values
__device__ float g_xr [(size_t)MTOK * DIM];
__device__ float g_wqr[(size_t)QKVN * DIM];
__device__ float g_wor[(size_t)DIM  * DIM];

// ---------------------------------------------------------------- helpers
__device__ __forceinline__ unsigned f2tf(float x) {
    unsigned r;
    asm("cvt.rna.tf32.f32 %0, %1;" : "=r"(r) : "f"(x));
    return r;
}

__device__ __forceinline__ void mma_tf32(float* c, const unsigned* a,
                                         unsigned b0, unsigned b1) {
    asm volatile(
        "mma.sync.aligned.m16n8k8.row.col.f32.tf32.tf32.f32 "
        "{%0,%1,%2,%3},{%4,%5,%6,%7},{%8,%9},{%0,%1,%2,%3};"
        : "+f"(c[0]), "+f"(c[1]), "+f"(c[2]), "+f"(c[3])
        : "r"(a[0]), "r"(a[1]), "r"(a[2]), "r"(a[3]), "r"(b0), "r"(b1));
}

__device__ __forceinline__ void cp16(void* smem_dst, const void* gmem_src) {
    unsigned s = (unsigned)__cvta_generic_to_shared(smem_dst);
    asm volatile("cp.async.cg.shared.global [%0], [%1], 16;\n" :: "r"(s), "l"(gmem_src));
}
__device__ __forceinline__ void cp_commit() {
    asm volatile("cp.async.commit_group;\n");
}
template <int N>
__device__ __forceinline__ void cp_wait() {
    asm volatile("cp.async.wait_group %0;\n" :: "n"(N));
}

// ----------------------------------------------------------------------------
// Pre-pass: round fp32 -> rna-tf32
// ----------------------------------------------------------------------------
__global__ void round_tf32_kernel(const float* __restrict__ in,
                                  float* __restrict__ out, int n4) {
    int i = blockIdx.x * blockDim.x + threadIdx.x;
    if (i < n4) {
        float4 v = ((const float4*)in)[i];
        float4 o;
        o.x = __uint_as_float(f2tf(v.x));
        o.y = __uint_as_float(f2tf(v.y));
        o.z = __uint_as_float(f2tf(v.z));
        o.w = __uint_as_float(f2tf(v.w));
        ((float4*)out)[i] = o;
    }
}

// ----------------------------------------------------------------------------
// C[M,N] = A[M,K] @ B[N,K]^T  via tf32 mma.
// 128x128 block, BK=32, 256 thr, 3-stage cp.async ring, ONE barrier per chunk.
// smem rows are 32 floats with xor swizzle (granule ^ (row&7)) -> conflict-free
// for STS.128 writes and quad fragment LDS reads. 16KB/stage/matrix.
// Inputs must be pre-rounded tf32 values (no cvt in mainloop).
// ----------------------------------------------------------------------------
#define G_STAGE  (128 * 32)                 // floats per stage per matrix
#define GEMM_SMEM (6 * G_STAGE * 4)         // 3 stages x (A+B) = 96 KB

template <bool ROUND>
__global__ void __launch_bounds__(256, 2)
gemm_tf32_kernel(const float* __restrict__ A, const float* __restrict__ B,
                 float* __restrict__ C, int M, int N, int K) {
    extern __shared__ float gsm[];
    float* Asm = gsm;                 // [3][128][32] swizzled
    float* Bsm = gsm + 3 * G_STAGE;   // [3][128][32] swizzled

    const int tid  = threadIdx.x;
    const int lane = tid & 31;
    const int warp = tid >> 5;
    const int g    = lane >> 2;
    const int tg   = lane & 3;
    const int wm   = (warp >> 2) * 64;
    const int wn   = (warp & 3) * 32;
    const int m0   = blockIdx.y * 128;
    const int n0   = blockIdx.x * 128;

    const int ldr = tid >> 3;          // 0..31
    const int ldb = tid & 7;           // granule 0..7

    float c[4][4][4];
#pragma unroll
    for (int mt = 0; mt < 4; mt++)
#pragma unroll
        for (int nt = 0; nt < 4; nt++)
#pragma unroll
            for (int i = 0; i < 4; i++) c[mt][nt][i] = 0.0f;

    const int nIter = K >> 5;

    // load chunk `ch` into stage `s`
    auto load_chunk = [&](int s, int ch) {
        float* As = Asm + s * G_STAGE;
        float* Bs = Bsm + s * G_STAGE;
        const int k0 = ch << 5;
#pragma unroll
        for (int i = 0; i < 4; i++) {
            int r  = ldr + i * 32;
            int sc = ((ldb ^ (r & 7)) << 2);
            cp16(&As[r * 32 + sc], &A[(size_t)(m0 + r) * K + k0 + ldb * 4]);
            cp16(&Bs[r * 32 + sc], &B[(size_t)(n0 + r) * K + k0 + ldb * 4]);
        }
        cp_commit();
    };

    load_chunk(0, 0);
    load_chunk(1, 1);

#pragma unroll 1
    for (int it = 0; it < nIter; it++) {
        if (it + 1 < nIter) cp_wait<1>(); else cp_wait<0>();
        __syncthreads();
        if (it + 2 < nIter) load_chunk((it + 2) % 3, it + 2);

        const unsigned* As = (const unsigned*)(Asm + (it % 3) * G_STAGE);
        const unsigned* Bs = (const unsigned*)(Bsm + (it % 3) * G_STAGE);
#pragma unroll
        for (int k8 = 0; k8 < 4; k8++) {
            const int gr0 = (k8 * 8) >> 2;       // granule of kc
            unsigned a[4][4], b[4][2];
#pragma unroll
            for (int mt = 0; mt < 4; mt++) {
                int r0 = wm + mt * 16 + g;
                int r1 = r0 + 8;
                int s0 = r0 & 7, s1 = r1 & 7;
                a[mt][0] = As[r0 * 32 + ((gr0 ^ s0) << 2) + tg];
                a[mt][1] = As[r1 * 32 + ((gr0 ^ s1) << 2) + tg];
                a[mt][2] = As[r0 * 32 + (((gr0 + 1) ^ s0) << 2) + tg];
                a[mt][3] = As[r1 * 32 + (((gr0 + 1) ^ s1) << 2) + tg];
            }
#pragma unroll
            for (int nt = 0; nt < 4; nt++) {
                int r = wn + nt * 8 + g;
                int s = r & 7;
                b[nt][0] = Bs[r * 32 + ((gr0 ^ s) << 2) + tg];
                b[nt][1] = Bs[r * 32 + (((gr0 + 1) ^ s) << 2) + tg];
            }
#pragma unroll
            for (int mt = 0; mt < 4; mt++)
#pragma unroll
                for (int nt = 0; nt < 4; nt++)
                    mma_tf32(c[mt][nt], a[mt], b[nt][0], b[nt][1]);
        }
    }

#pragma unroll
    for (int mt = 0; mt < 4; mt++)
#pragma unroll
        for (int nt = 0; nt < 4; nt++) {
            int row = m0 + wm + mt * 16 + g;
            int col = n0 + wn + nt * 8 + tg * 2;
            float v0 = c[mt][nt][0], v1 = c[mt][nt][1];
            float v2 = c[mt][nt][2], v3 = c[mt][nt][3];
            if (ROUND) {
                v0 = __uint_as_float(f2tf(v0));
                v1 = __uint_as_float(f2tf(v1));
                v2 = __uint_as_float(f2tf(v2));
                v3 = __uint_as_float(f2tf(v3));
            }
            *(float2*)&C[(size_t)row * N + col]       = make_float2(v0, v1);
            *(float2*)&C[(size_t)(row + 8) * N + col] = make_float2(v2, v3);
        }
}

// ----------------------------------------------------------------------------
// Flash attention (causal), tf32 mma, 2-stage cp.async K/V pipeline, occ=2.
// ----------------------------------------------------------------------------
#define QP_PAD 68
#define K_PAD  68
#define V_PAD  72
#define K_STAGE (64 * K_PAD)
#define V_STAGE (64 * V_PAD)
#define ATTN_SMEM ((128 * QP_PAD + 2 * K_STAGE + 2 * V_STAGE) * 4)

__device__ __forceinline__ void attn_prefetch(float* Ks, float* Vs,
                                              const float* __restrict__ qkv,
                                              size_t tok0, int h, int kt,
                                              int stage, int tid) {
#pragma unroll
    for (int i = 0; i < 4; i++) {
        int idx = tid + i * 256;
        int r   = idx >> 4;
        int c4  = (idx & 15) * 4;
        const float* base = &qkv[(tok0 + kt * 64 + r) * (size_t)QKVN + h * HD + c4];
        cp16(&Ks[stage * K_STAGE + r * K_PAD + c4], base + DIM);
        cp16(&Vs[stage * V_STAGE + r * V_PAD + c4], base + 2 * DIM);
    }
    cp_commit();
}

__global__ void __launch_bounds__(256, 2)
attn_tf32_kernel(const float* __restrict__ qkv, float* __restrict__ att) {
    extern __shared__ float smf[];
    float* Qs = smf;                          // [128][QP_PAD]; reused as Ps
    float* Ks = smf + 128 * QP_PAD;           // [2][64][K_PAD]
    float* Vs = Ks + 2 * K_STAGE;             // [2][64][V_PAD]

    const int tid  = threadIdx.x;
    const int lane = tid & 31;
    const int warp = tid >> 5;
    const int g    = lane >> 2;
    const int tg   = lane & 3;
    const int bq   = gridDim.x - 1 - blockIdx.x;   // largest tiles first
    const int bh   = blockIdx.y;
    const int b    = bh >> 4;
    const int h    = bh & 15;
    const size_t tok0 = (size_t)b * SEQ;
    const int qr   = warp * 16;

    const int ktmax = 2 * bq + 2;

    attn_prefetch(Ks, Vs, qkv, tok0, h, 0, 0, tid);

    // Q: pre-rounded; *0.125 is exact
#pragma unroll
    for (int i = 0; i < 8; i++) {
        int idx = tid + i * 256;
        int r   = idx >> 4;
        int c4  = (idx & 15) * 4;
        float4 v = *(const float4*)&qkv[(tok0 + bq * 128 + r) * QKVN + h * HD + c4];
        Qs[r * QP_PAD + c4 + 0] = v.x * 0.125f;
        Qs[r * QP_PAD + c4 + 1] = v.y * 0.125f;
        Qs[r * QP_PAD + c4 + 2] = v.z * 0.125f;
        Qs[r * QP_PAD + c4 + 3] = v.w * 0.125f;
    }
    __syncthreads();

    unsigned qf[8][4];
    {
        const unsigned* Qu = (const unsigned*)Qs;
#pragma unroll
        for (int k8 = 0; k8 < 8; k8++) {
            int kc = k8 * 8;
            qf[k8][0] = Qu[(qr + g) * QP_PAD + kc + tg];
            qf[k8][1] = Qu[(qr + g + 8) * QP_PAD + kc + tg];
            qf[k8][2] = Qu[(qr + g) * QP_PAD + kc + tg + 4];
            qf[k8][3] = Qu[(qr + g + 8) * QP_PAD + kc + tg + 4];
        }
    }
    __syncthreads();

    unsigned* Ps = (unsigned*)Qs;

    float oacc[8][4];
#pragma unroll
    for (int n = 0; n < 8; n++)
#pragma unroll
        for (int i = 0; i < 4; i++) oacc[n][i] = 0.0f;
    float mrow[2] = {-INFINITY, -INFINITY};
    float lrow[2] = {0.0f, 0.0f};

    const int r0g = bq * 128 + qr + g;
    const int r1g = r0g + 8;

#pragma unroll 1
    for (int kt = 0; kt < ktmax; kt++) {
        if (kt + 1 < ktmax) {
            attn_prefetch(Ks, Vs, qkv, tok0, h, kt + 1, (kt + 1) & 1, tid);
            cp_wait<1>();
        } else {
            cp_wait<0>();
        }
        __syncthreads();

        const unsigned* Kst = (const unsigned*)(Ks + (kt & 1) * K_STAGE);
        const unsigned* Vst = (const unsigned*)(Vs + (kt & 1) * V_STAGE);

        float sacc[8][4];
#pragma unroll
        for (int n = 0; n < 8; n++)
#pragma unroll
            for (int i = 0; i < 4; i++) sacc[n][i] = 0.0f;
#pragma unroll
        for (int k8 = 0; k8 < 8; k8++) {
            int kc = k8 * 8;
#pragma unroll
            for (int n = 0; n < 8; n++) {
                unsigned b0 = Kst[(n * 8 + g) * K_PAD + kc + tg];
                unsigned b1 = Kst[(n * 8 + g) * K_PAD + kc + tg + 4];
                mma_tf32(sacc[n], qf[k8], b0, b1);
            }
        }

        if (kt >= 2 * bq) {
#pragma unroll
            for (int n = 0; n < 8; n++) {
#pragma unroll
                for (int ci = 0; ci < 4; ci++) {
                    int col = kt * 64 + n * 8 + tg * 2 + (ci & 1);
                    int rowg = (ci < 2) ? r0g : r1g;
                    if (col > rowg) sacc[n][ci] = -INFINITY;
                }
            }
        }

        float mx0 = -INFINITY, mx1 = -INFINITY;
#pragma unroll
        for (int n = 0; n < 8; n++) {
            mx0 = fmaxf(mx0, fmaxf(sacc[n][0], sacc[n][1]));
            mx1 = fmaxf(mx1, fmaxf(sacc[n][2], sacc[n][3]));
        }
#pragma unroll
        for (int off = 1; off <= 2; off <<= 1) {
            mx0 = fmaxf(mx0, __shfl_xor_sync(0xffffffffu, mx0, off));
            mx1 = fmaxf(mx1, __shfl_xor_sync(0xffffffffu, mx1, off));
        }
        float mn0 = fmaxf(mrow[0], mx0);
        float mn1 = fmaxf(mrow[1], mx1);
        float al0 = __expf(mrow[0] - mn0);
        float al1 = __expf(mrow[1] - mn1);

        float rs0 = 0.0f, rs1 = 0.0f;
#pragma unroll
        for (int n = 0; n < 8; n++) {
            sacc[n][0] = __expf(sacc[n][0] - mn0);
            sacc[n][1] = __expf(sacc[n][1] - mn0);
            sacc[n][2] = __expf(sacc[n][2] - mn1);
            sacc[n][3] = __expf(sacc[n][3] - mn1);
            rs0 += sacc[n][0] + sacc[n][1];
            rs1 += sacc[n][2] + sacc[n][3];
        }
#pragma unroll
        for (int off = 1; off <= 2; off <<= 1) {
            rs0 += __shfl_xor_sync(0xffffffffu, rs0, off);
            rs1 += __shfl_xor_sync(0xffffffffu, rs1, off);
        }
        lrow[0] = lrow[0] * al0 + rs0;
        lrow[1] = lrow[1] * al1 + rs1;
        mrow[0] = mn0;
        mrow[1] = mn1;
#pragma unroll
        for (int n = 0; n < 8; n++) {
            oacc[n][0] *= al0; oacc[n][1] *= al0;
            oacc[n][2] *= al1; oacc[n][3] *= al1;
        }

#pragma unroll
        for (int n = 0; n < 8; n++) {
            *(uint2*)&Ps[(qr + g) * QP_PAD + n * 8 + tg * 2] =
                make_uint2(f2tf(sacc[n][0]), f2tf(sacc[n][1]));
            *(uint2*)&Ps[(qr + g + 8) * QP_PAD + n * 8 + tg * 2] =
                make_uint2(f2tf(sacc[n][2]), f2tf(sacc[n][3]));
        }
        __syncwarp();

#pragma unroll
        for (int k8 = 0; k8 < 8; k8++) {
            int kc = k8 * 8;
            unsigned pa[4];
            pa[0] = Ps[(qr + g) * QP_PAD + kc + tg];
            pa[1] = Ps[(qr + g + 8) * QP_PAD + kc + tg];
            pa[2] = Ps[(qr + g) * QP_PAD + kc + tg + 4];
            pa[3] = Ps[(qr + g + 8) * QP_PAD + kc + tg + 4];
#pragma unroll
            for (int n = 0; n < 8; n++) {
                unsigned b0 = Vst[(kc + tg) * V_PAD + n * 8 + g];
                unsigned b1 = Vst[(kc + tg + 4) * V_PAD + n * 8 + g];
                mma_tf32(oacc[n], pa, b0, b1);
            }
        }
        __syncthreads();
    }

    float inv0 = 1.0f / lrow[0];
    float inv1 = 1.0f / lrow[1];
    size_t row0 = tok0 + bq * 128 + qr + g;
#pragma unroll
    for (int n = 0; n < 8; n++) {
        int col = h * HD + n * 8 + tg * 2;
        *(float2*)&att[row0 * DIM + col] =
            make_float2(__uint_as_float(f2tf(oacc[n][0] * inv0)),
                        __uint_as_float(f2tf(oacc[n][1] * inv0)));
        *(float2*)&att[(row0 + 8) * DIM + col] =
            make_float2(__uint_as_float(f2tf(oacc[n][2] * inv1)),
                        __uint_as_float(f2tf(oacc[n][3] * inv1)));
    }
}

// ----------------------------------------------------------------------------
extern "C" void kernel_launch(void* const* d_in, const int* in_sizes, int n_in,
                              void* d_out, int out_size) {
    const float* x     = (const float*)d_in[0];
    const float* W_qkv = (const float*)d_in[1];
    const float* W_out = (const float*)d_in[2];
    float* out = (float*)d_out;

    float *qkv_buf, *att_buf, *xr, *wqr, *wor;
    cudaGetSymbolAddress((void**)&qkv_buf, g_qkv);
    cudaGetSymbolAddress((void**)&att_buf, g_att);
    cudaGetSymbolAddress((void**)&xr,  g_xr);
    cudaGetSymbolAddress((void**)&wqr, g_wqr);
    cudaGetSymbolAddress((void**)&wor, g_wor);

    cudaFuncSetAttribute(gemm_tf32_kernel<true>,
                         cudaFuncAttributeMaxDynamicSharedMemorySize, GEMM_SMEM);
    cudaFuncSetAttribute(gemm_tf32_kernel<false>,
                         cudaFuncAttributeMaxDynamicSharedMemorySize, GEMM_SMEM);
    cudaFuncSetAttribute(attn_tf32_kernel,
                         cudaFuncAttributeMaxDynamicSharedMemorySize, ATTN_SMEM);

    // 0) One-time rounding pre-pass
    {
        int n4x = MTOK * DIM / 4;
        round_tf32_kernel<<<(n4x + 255) / 256, 256>>>(x, xr, n4x);
        int n4q = QKVN * DIM / 4;
        round_tf32_kernel<<<(n4q + 255) / 256, 256>>>(W_qkv, wqr, n4q);
        int n4o = DIM * DIM / 4;
        round_tf32_kernel<<<(n4o + 255) / 256, 256>>>(W_out, wor, n4o);
    }

    // 1) QKV projection
    {
        dim3 grid(QKVN / 128, MTOK / 128);
        gemm_tf32_kernel<true><<<grid, 256, GEMM_SMEM>>>(xr, wqr, qkv_buf, MTOK, QKVN, DIM);
    }
    // 2) Causal flash attention
    {
        dim3 grid(SEQ / 128, BSZ * NH);
        attn_tf32_kernel<<<grid, 256, ATTN_SMEM>>>(qkv_buf, att_buf);
    }
    // 3) Output projection
    {
        dim3 grid(DIM / 128, MTOK / 128);
        gemm_tf32_kernel<false><<<grid, 256, GEMM_SMEM>>>(att_buf, wor, out, MTOK, DIM, DIM);
    }
}

// round 15
// speedup vs baseline: 5.0056x; 1.0070x over previous
#include <cuda_runtime.h>
#include <math.h>
#include <stdint.h>

#define BSZ   2
#define SEQ   2048
#define DIM   1024
#define NH    16
#define HD    64
#define MTOK  (BSZ * SEQ)       // 4096
#define QKVN  (3 * DIM)         // 3072

// Scratch (no cudaMalloc allowed)
__device__ float g_qkv[(size_t)MTOK * QKVN];   // rna-tf32 values
__device__ float g_att[(size_t)MTOK * DIM];    // rna-tf32 values
__device__ float g_xr [(size_t)MTOK * DIM];
__device__ float g_wqr[(size_t)QKVN * DIM];
__device__ float g_wor[(size_t)DIM  * DIM];

// ---------------------------------------------------------------- helpers
__device__ __forceinline__ unsigned f2tf(float x) {
    unsigned r;
    asm("cvt.rna.tf32.f32 %0, %1;" : "=r"(r) : "f"(x));
    return r;
}

__device__ __forceinline__ void mma_tf32(float* c, const unsigned* a,
                                         unsigned b0, unsigned b1) {
    asm volatile(
        "mma.sync.aligned.m16n8k8.row.col.f32.tf32.tf32.f32 "
        "{%0,%1,%2,%3},{%4,%5,%6,%7},{%8,%9},{%0,%1,%2,%3};"
        : "+f"(c[0]), "+f"(c[1]), "+f"(c[2]), "+f"(c[3])
        : "r"(a[0]), "r"(a[1]), "r"(a[2]), "r"(a[3]), "r"(b0), "r"(b1));
}

__device__ __forceinline__ void cp16(void* smem_dst, const void* gmem_src) {
    unsigned s = (unsigned)__cvta_generic_to_shared(smem_dst);
    asm volatile("cp.async.cg.shared.global [%0], [%1], 16;\n" :: "r"(s), "l"(gmem_src));
}
__device__ __forceinline__ void cp_commit() {
    asm volatile("cp.async.commit_group;\n");
}
template <int N>
__device__ __forceinline__ void cp_wait() {
    asm volatile("cp.async.wait_group %0;\n" :: "n"(N));
}

// ----------------------------------------------------------------------------
// Pre-pass: round fp32 -> rna-tf32
// ----------------------------------------------------------------------------
__global__ void round_tf32_kernel(const float* __restrict__ in,
                                  float* __restrict__ out, int n4) {
    int i = blockIdx.x * blockDim.x + threadIdx.x;
    if (i < n4) {
        float4 v = ((const float4*)in)[i];
        float4 o;
        o.x = __uint_as_float(f2tf(v.x));
        o.y = __uint_as_float(f2tf(v.y));
        o.z = __uint_as_float(f2tf(v.z));
        o.w = __uint_as_float(f2tf(v.w));
        ((float4*)out)[i] = o;
    }
}

// ----------------------------------------------------------------------------
// C[M,N] = A[M,K] @ B[N,K]^T  via tf32 mma.  (unchanged from R8 — proven)
// 128x128 block, BK=32, 256 thr, 3-stage cp.async ring, ONE barrier per chunk.
// xor-swizzled 32-float smem rows; inputs pre-rounded tf32.
// ----------------------------------------------------------------------------
#define G_STAGE  (128 * 32)
#define GEMM_SMEM (6 * G_STAGE * 4)         // 96 KB

template <bool ROUND>
__global__ void __launch_bounds__(256, 2)
gemm_tf32_kernel(const float* __restrict__ A, const float* __restrict__ B,
                 float* __restrict__ C, int M, int N, int K) {
    extern __shared__ float gsm[];
    float* Asm = gsm;                 // [3][128][32] swizzled
    float* Bsm = gsm + 3 * G_STAGE;

    const int tid  = threadIdx.x;
    const int lane = tid & 31;
    const int warp = tid >> 5;
    const int g    = lane >> 2;
    const int tg   = lane & 3;
    const int wm   = (warp >> 2) * 64;
    const int wn   = (warp & 3) * 32;
    const int m0   = blockIdx.y * 128;
    const int n0   = blockIdx.x * 128;

    const int ldr = tid >> 3;
    const int ldb = tid & 7;

    float c[4][4][4];
#pragma unroll
    for (int mt = 0; mt < 4; mt++)
#pragma unroll
        for (int nt = 0; nt < 4; nt++)
#pragma unroll
            for (int i = 0; i < 4; i++) c[mt][nt][i] = 0.0f;

    const int nIter = K >> 5;

    auto load_chunk = [&](int s, int ch) {
        float* As = Asm + s * G_STAGE;
        float* Bs = Bsm + s * G_STAGE;
        const int k0 = ch << 5;
#pragma unroll
        for (int i = 0; i < 4; i++) {
            int r  = ldr + i * 32;
            int sc = ((ldb ^ (r & 7)) << 2);
            cp16(&As[r * 32 + sc], &A[(size_t)(m0 + r) * K + k0 + ldb * 4]);
            cp16(&Bs[r * 32 + sc], &B[(size_t)(n0 + r) * K + k0 + ldb * 4]);
        }
        cp_commit();
    };

    load_chunk(0, 0);
    load_chunk(1, 1);

#pragma unroll 1
    for (int it = 0; it < nIter; it++) {
        if (it + 1 < nIter) cp_wait<1>(); else cp_wait<0>();
        __syncthreads();
        if (it + 2 < nIter) load_chunk((it + 2) % 3, it + 2);

        const unsigned* As = (const unsigned*)(Asm + (it % 3) * G_STAGE);
        const unsigned* Bs = (const unsigned*)(Bsm + (it % 3) * G_STAGE);
#pragma unroll
        for (int k8 = 0; k8 < 4; k8++) {
            const int gr0 = (k8 * 8) >> 2;
            unsigned a[4][4], b[4][2];
#pragma unroll
            for (int mt = 0; mt < 4; mt++) {
                int r0 = wm + mt * 16 + g;
                int r1 = r0 + 8;
                int s0 = r0 & 7, s1 = r1 & 7;
                a[mt][0] = As[r0 * 32 + ((gr0 ^ s0) << 2) + tg];
                a[mt][1] = As[r1 * 32 + ((gr0 ^ s1) << 2) + tg];
                a[mt][2] = As[r0 * 32 + (((gr0 + 1) ^ s0) << 2) + tg];
                a[mt][3] = As[r1 * 32 + (((gr0 + 1) ^ s1) << 2) + tg];
            }
#pragma unroll
            for (int nt = 0; nt < 4; nt++) {
                int r = wn + nt * 8 + g;
                int s = r & 7;
                b[nt][0] = Bs[r * 32 + ((gr0 ^ s) << 2) + tg];
                b[nt][1] = Bs[r * 32 + (((gr0 + 1) ^ s) << 2) + tg];
            }
#pragma unroll
            for (int mt = 0; mt < 4; mt++)
#pragma unroll
                for (int nt = 0; nt < 4; nt++)
                    mma_tf32(c[mt][nt], a[mt], b[nt][0], b[nt][1]);
        }
    }

#pragma unroll
    for (int mt = 0; mt < 4; mt++)
#pragma unroll
        for (int nt = 0; nt < 4; nt++) {
            int row = m0 + wm + mt * 16 + g;
            int col = n0 + wn + nt * 8 + tg * 2;
            float v0 = c[mt][nt][0], v1 = c[mt][nt][1];
            float v2 = c[mt][nt][2], v3 = c[mt][nt][3];
            if (ROUND) {
                v0 = __uint_as_float(f2tf(v0));
                v1 = __uint_as_float(f2tf(v1));
                v2 = __uint_as_float(f2tf(v2));
                v3 = __uint_as_float(f2tf(v3));
            }
            *(float2*)&C[(size_t)row * N + col]       = make_float2(v0, v1);
            *(float2*)&C[(size_t)(row + 8) * N + col] = make_float2(v2, v3);
        }
}

// ----------------------------------------------------------------------------
// Flash attention (causal), tf32 mma, 2-stage cp.async, occ=2.
// ONE barrier per kt; warp-level skip of fully-masked tiles.
// FIX vs failed R9: mask guard uses warp MIN row (mask iff tile max col >
// warp min row). Previous max-row guard let the diagonal-edge warp leak
// future keys (rel_err 7.8e-2).
// ----------------------------------------------------------------------------
#define QP_PAD 68
#define K_PAD  68
#define V_PAD  72
#define K_STAGE (64 * K_PAD)
#define V_STAGE (64 * V_PAD)
#define ATTN_SMEM ((128 * QP_PAD + 2 * K_STAGE + 2 * V_STAGE) * 4)

__device__ __forceinline__ void attn_prefetch(float* Ks, float* Vs,
                                              const float* __restrict__ qkv,
                                              size_t tok0, int h, int kt,
                                              int stage, int tid) {
#pragma unroll
    for (int i = 0; i < 4; i++) {
        int idx = tid + i * 256;
        int r   = idx >> 4;
        int c4  = (idx & 15) * 4;
        const float* base = &qkv[(tok0 + kt * 64 + r) * (size_t)QKVN + h * HD + c4];
        cp16(&Ks[stage * K_STAGE + r * K_PAD + c4], base + DIM);
        cp16(&Vs[stage * V_STAGE + r * V_PAD + c4], base + 2 * DIM);
    }
    cp_commit();
}

__global__ void __launch_bounds__(256, 2)
attn_tf32_kernel(const float* __restrict__ qkv, float* __restrict__ att) {
    extern __shared__ float smf[];
    float* Qs = smf;                          // [128][QP_PAD]; reused as Ps
    float* Ks = smf + 128 * QP_PAD;           // [2][64][K_PAD]
    float* Vs = Ks + 2 * K_STAGE;             // [2][64][V_PAD]

    const int tid  = threadIdx.x;
    const int lane = tid & 31;
    const int warp = tid >> 5;
    const int g    = lane >> 2;
    const int tg   = lane & 3;
    const int bq   = gridDim.x - 1 - blockIdx.x;   // largest tiles first
    const int bh   = blockIdx.y;
    const int b    = bh >> 4;
    const int h    = bh & 15;
    const size_t tok0 = (size_t)b * SEQ;
    const int qr   = warp * 16;

    const int ktmax = 2 * bq + 2;

    attn_prefetch(Ks, Vs, qkv, tok0, h, 0, 0, tid);

    // Q: pre-rounded; *0.125 is exact
#pragma unroll
    for (int i = 0; i < 8; i++) {
        int idx = tid + i * 256;
        int r   = idx >> 4;
        int c4  = (idx & 15) * 4;
        float4 v = *(const float4*)&qkv[(tok0 + bq * 128 + r) * QKVN + h * HD + c4];
        Qs[r * QP_PAD + c4 + 0] = v.x * 0.125f;
        Qs[r * QP_PAD + c4 + 1] = v.y * 0.125f;
        Qs[r * QP_PAD + c4 + 2] = v.z * 0.125f;
        Qs[r * QP_PAD + c4 + 3] = v.w * 0.125f;
    }
    __syncthreads();

    unsigned qf[8][4];
    {
        const unsigned* Qu = (const unsigned*)Qs;
#pragma unroll
        for (int k8 = 0; k8 < 8; k8++) {
            int kc = k8 * 8;
            qf[k8][0] = Qu[(qr + g) * QP_PAD + kc + tg];
            qf[k8][1] = Qu[(qr + g + 8) * QP_PAD + kc + tg];
            qf[k8][2] = Qu[(qr + g) * QP_PAD + kc + tg + 4];
            qf[k8][3] = Qu[(qr + g + 8) * QP_PAD + kc + tg + 4];
        }
    }
    __syncthreads();

    unsigned* Ps = (unsigned*)Qs;

    float oacc[8][4];
#pragma unroll
    for (int n = 0; n < 8; n++)
#pragma unroll
        for (int i = 0; i < 4; i++) oacc[n][i] = 0.0f;
    float mrow[2] = {-INFINITY, -INFINITY};
    float lrow[2] = {0.0f, 0.0f};

    const int r0g = bq * 128 + qr + g;
    const int r1g = r0g + 8;
    const int warp_row_min = bq * 128 + qr;        // warp's first q row
    const int warp_row_max = warp_row_min + 15;    // warp's last q row

#pragma unroll 1
    for (int kt = 0; kt < ktmax; kt++) {
        // Only group `kt` can be outstanding here -> wait<0> exact.
        cp_wait<0>();
        __syncthreads();   // all warps done with iter kt-1 -> stage (kt+1)&1 free
        if (kt + 1 < ktmax)
            attn_prefetch(Ks, Vs, qkv, tok0, h, kt + 1, (kt + 1) & 1, tid);

        // Fully-masked tile for this warp (all cols > all rows) contributes 0.
        if (warp_row_max < kt * 64) continue;

        const unsigned* Kst = (const unsigned*)(Ks + (kt & 1) * K_STAGE);
        const unsigned* Vst = (const unsigned*)(Vs + (kt & 1) * V_STAGE);

        float sacc[8][4];
#pragma unroll
        for (int n = 0; n < 8; n++)
#pragma unroll
            for (int i = 0; i < 4; i++) sacc[n][i] = 0.0f;
#pragma unroll
        for (int k8 = 0; k8 < 8; k8++) {
            int kc = k8 * 8;
#pragma unroll
            for (int n = 0; n < 8; n++) {
                unsigned b0 = Kst[(n * 8 + g) * K_PAD + kc + tg];
                unsigned b1 = Kst[(n * 8 + g) * K_PAD + kc + tg + 4];
                mma_tf32(sacc[n], qf[k8], b0, b1);
            }
        }

        // Mask iff tile max col can exceed warp MIN row (diagonal intersects).
        if (kt * 64 + 63 > warp_row_min) {
#pragma unroll
            for (int n = 0; n < 8; n++) {
#pragma unroll
                for (int ci = 0; ci < 4; ci++) {
                    int col = kt * 64 + n * 8 + tg * 2 + (ci & 1);
                    int rowg = (ci < 2) ? r0g : r1g;
                    if (col > rowg) sacc[n][ci] = -INFINITY;
                }
            }
        }

        float mx0 = -INFINITY, mx1 = -INFINITY;
#pragma unroll
        for (int n = 0; n < 8; n++) {
            mx0 = fmaxf(mx0, fmaxf(sacc[n][0], sacc[n][1]));
            mx1 = fmaxf(mx1, fmaxf(sacc[n][2], sacc[n][3]));
        }
#pragma unroll
        for (int off = 1; off <= 2; off <<= 1) {
            mx0 = fmaxf(mx0, __shfl_xor_sync(0xffffffffu, mx0, off));
            mx1 = fmaxf(mx1, __shfl_xor_sync(0xffffffffu, mx1, off));
        }
        float mn0 = fmaxf(mrow[0], mx0);
        float mn1 = fmaxf(mrow[1], mx1);
        float al0 = __expf(mrow[0] - mn0);
        float al1 = __expf(mrow[1] - mn1);

        float rs0 = 0.0f, rs1 = 0.0f;
#pragma unroll
        for (int n = 0; n < 8; n++) {
            sacc[n][0] = __expf(sacc[n][0] - mn0);
            sacc[n][1] = __expf(sacc[n][1] - mn0);
            sacc[n][2] = __expf(sacc[n][2] - mn1);
            sacc[n][3] = __expf(sacc[n][3] - mn1);
            rs0 += sacc[n][0] + sacc[n][1];
            rs1 += sacc[n][2] + sacc[n][3];
        }
#pragma unroll
        for (int off = 1; off <= 2; off <<= 1) {
            rs0 += __shfl_xor_sync(0xffffffffu, rs0, off);
            rs1 += __shfl_xor_sync(0xffffffffu, rs1, off);
        }
        lrow[0] = lrow[0] * al0 + rs0;
        lrow[1] = lrow[1] * al1 + rs1;
        mrow[0] = mn0;
        mrow[1] = mn1;
#pragma unroll
        for (int n = 0; n < 8; n++) {
            oacc[n][0] *= al0; oacc[n][1] *= al0;
            oacc[n][2] *= al1; oacc[n][3] *= al1;
        }

#pragma unroll
        for (int n = 0; n < 8; n++) {
            *(uint2*)&Ps[(qr + g) * QP_PAD + n * 8 + tg * 2] =
                make_uint2(f2tf(sacc[n][0]), f2tf(sacc[n][1]));
            *(uint2*)&Ps[(qr + g + 8) * QP_PAD + n * 8 + tg * 2] =
                make_uint2(f2tf(sacc[n][2]), f2tf(sacc[n][3]));
        }
        __syncwarp();

#pragma unroll
        for (int k8 = 0; k8 < 8; k8++) {
            int kc = k8 * 8;
            unsigned pa[4];
            pa[0] = Ps[(qr + g) * QP_PAD + kc + tg];
            pa[1] = Ps[(qr + g + 8) * QP_PAD + kc + tg];
            pa[2] = Ps[(qr + g) * QP_PAD + kc + tg + 4];
            pa[3] = Ps[(qr + g + 8) * QP_PAD + kc + tg + 4];
#pragma unroll
            for (int n = 0; n < 8; n++) {
                unsigned b0 = Vst[(kc + tg) * V_PAD + n * 8 + g];
                unsigned b1 = Vst[(kc + tg + 4) * V_PAD + n * 8 + g];
                mma_tf32(oacc[n], pa, b0, b1);
            }
        }
    }

    float inv0 = 1.0f / lrow[0];
    float inv1 = 1.0f / lrow[1];
    size_t row0 = tok0 + bq * 128 + qr + g;
#pragma unroll
    for (int n = 0; n < 8; n++) {
        int col = h * HD + n * 8 + tg * 2;
        *(float2*)&att[row0 * DIM + col] =
            make_float2(__uint_as_float(f2tf(oacc[n][0] * inv0)),
                        __uint_as_float(f2tf(oacc[n][1] * inv0)));
        *(float2*)&att[(row0 + 8) * DIM + col] =
            make_float2(__uint_as_float(f2tf(oacc[n][2] * inv1)),
                        __uint_as_float(f2tf(oacc[n][3] * inv1)));
    }
}

// ----------------------------------------------------------------------------
extern "C" void kernel_launch(void* const* d_in, const int* in_sizes, int n_in,
                              void* d_out, int out_size) {
    const float* x     = (const float*)d_in[0];
    const float* W_qkv = (const float*)d_in[1];
    const float* W_out = (const float*)d_in[2];
    float* out = (float*)d_out;

    float *qkv_buf, *att_buf, *xr, *wqr, *wor;
    cudaGetSymbolAddress((void**)&qkv_buf, g_qkv);
    cudaGetSymbolAddress((void**)&att_buf, g_att);
    cudaGetSymbolAddress((void**)&xr,  g_xr);
    cudaGetSymbolAddress((void**)&wqr, g_wqr);
    cudaGetSymbolAddress((void**)&wor, g_wor);

    cudaFuncSetAttribute(gemm_tf32_kernel<true>,
                         cudaFuncAttributeMaxDynamicSharedMemorySize, GEMM_SMEM);
    cudaFuncSetAttribute(gemm_tf32_kernel<false>,
                         cudaFuncAttributeMaxDynamicSharedMemorySize, GEMM_SMEM);
    cudaFuncSetAttribute(attn_tf32_kernel,
                         cudaFuncAttributeMaxDynamicSharedMemorySize, ATTN_SMEM);

    // 0) One-time rounding pre-pass
    {
        int n4x = MTOK * DIM / 4;
        round_tf32_kernel<<<(n4x + 255) / 256, 256>>>(x, xr, n4x);
        int n4q = QKVN * DIM / 4;
        round_tf32_kernel<<<(n4q + 255) / 256, 256>>>(W_qkv, wqr, n4q);
        int n4o = DIM * DIM / 4;
        round_tf32_kernel<<<(n4o + 255) / 256, 256>>>(W_out, wor, n4o);
    }

    // 1) QKV projection
    {
        dim3 grid(QKVN / 128, MTOK / 128);
        gemm_tf32_kernel<true><<<grid, 256, GEMM_SMEM>>>(xr, wqr, qkv_buf, MTOK, QKVN, DIM);
    }
    // 2) Causal flash attention
    {
        dim3 grid(SEQ / 128, BSZ * NH);
        attn_tf32_kernel<<<grid, 256, ATTN_SMEM>>>(qkv_buf, att_buf);
    }
    // 3) Output projection
    {
        dim3 grid(DIM / 128, MTOK / 128);
        gemm_tf32_kernel<false><<<grid, 256, GEMM_SMEM>>>(att_buf, wor, out, MTOK, DIM, DIM);
    }
}

// round 16
// speedup vs baseline: 5.3544x; 1.0697x over previous
#include <cuda_runtime.h>
#include <math.h>
#include <stdint.h>

#define BSZ   2
#define SEQ   2048
#define DIM   1024
#define NH    16
#define HD    64
#define MTOK  (BSZ * SEQ)       // 4096
#define QKVN  (3 * DIM)         // 3072

// Scratch (no cudaMalloc allowed)
__device__ float g_qkv[(size_t)MTOK * QKVN];   // rna-tf32 values
__device__ float g_att[(size_t)MTOK * DIM];    // rna-tf32 values
__device__ float g_xr [(size_t)MTOK * DIM];
__device__ float g_wqr[(size_t)QKVN * DIM];
__device__ float g_wor[(size_t)DIM  * DIM];

// ---------------------------------------------------------------- helpers
__device__ __forceinline__ unsigned f2tf(float x) {
    unsigned r;
    asm("cvt.rna.tf32.f32 %0, %1;" : "=r"(r) : "f"(x));
    return r;
}

__device__ __forceinline__ void mma_tf32(float* c, const unsigned* a,
                                         unsigned b0, unsigned b1) {
    asm volatile(
        "mma.sync.aligned.m16n8k8.row.col.f32.tf32.tf32.f32 "
        "{%0,%1,%2,%3},{%4,%5,%6,%7},{%8,%9},{%0,%1,%2,%3};"
        : "+f"(c[0]), "+f"(c[1]), "+f"(c[2]), "+f"(c[3])
        : "r"(a[0]), "r"(a[1]), "r"(a[2]), "r"(a[3]), "r"(b0), "r"(b1));
}

// ldmatrix x4: four 8x8 b16 tiles; lanes 0-7/8-15/16-23/24-31 address tiles 0-3.
// For tf32, each lane's b16-pair in tile k == one tf32 fragment element.
__device__ __forceinline__ void ldsm4(unsigned& r0, unsigned& r1,
                                      unsigned& r2, unsigned& r3, uint32_t addr) {
    asm volatile("ldmatrix.sync.aligned.m8n8.x4.shared.b16 {%0,%1,%2,%3}, [%4];"
        : "=r"(r0), "=r"(r1), "=r"(r2), "=r"(r3) : "r"(addr));
}

__device__ __forceinline__ void cp16(void* smem_dst, const void* gmem_src) {
    unsigned s = (unsigned)__cvta_generic_to_shared(smem_dst);
    asm volatile("cp.async.cg.shared.global [%0], [%1], 16;\n" :: "r"(s), "l"(gmem_src));
}
__device__ __forceinline__ void cp_commit() {
    asm volatile("cp.async.commit_group;\n");
}
template <int N>
__device__ __forceinline__ void cp_wait() {
    asm volatile("cp.async.wait_group %0;\n" :: "n"(N));
}
__device__ __forceinline__ uint32_t smem_u32(const void* p) {
    return (uint32_t)__cvta_generic_to_shared(p);
}

// ----------------------------------------------------------------------------
// Pre-pass: round fp32 -> rna-tf32
// ----------------------------------------------------------------------------
__global__ void round_tf32_kernel(const float* __restrict__ in,
                                  float* __restrict__ out, int n4) {
    int i = blockIdx.x * blockDim.x + threadIdx.x;
    if (i < n4) {
        float4 v = ((const float4*)in)[i];
        float4 o;
        o.x = __uint_as_float(f2tf(v.x));
        o.y = __uint_as_float(f2tf(v.y));
        o.z = __uint_as_float(f2tf(v.z));
        o.w = __uint_as_float(f2tf(v.w));
        ((float4*)out)[i] = o;
    }
}

// ----------------------------------------------------------------------------
// C[M,N] = A[M,K] @ B[N,K]^T via tf32 mma, 3-stage cp.async ring, 1 barrier/chunk.
// Fragment loads via ldmatrix.x4 (6 LDSM per k8 instead of 24 LDS).
// xor-swizzled 32-float smem rows; inputs pre-rounded tf32.
// A-tile lane map: tiles {rows+0 gr, rows+8 gr, rows+0 gr+1, rows+8 gr+1}
// B-tile lane map: tiles {rows+0 gr, rows+0 gr+1, rows+8 gr, rows+8 gr+1}
// Swizzle: row&7 == lane&7 for all addressed rows (offsets are multiples of 8).
// ----------------------------------------------------------------------------
#define G_STAGE  (128 * 32)
#define GEMM_SMEM (6 * G_STAGE * 4)         // 96 KB

template <bool ROUND>
__global__ void __launch_bounds__(256, 2)
gemm_tf32_kernel(const float* __restrict__ A, const float* __restrict__ B,
                 float* __restrict__ C, int M, int N, int K) {
    extern __shared__ float gsm[];
    float* Asm = gsm;                 // [3][128][32] swizzled
    float* Bsm = gsm + 3 * G_STAGE;

    const int tid  = threadIdx.x;
    const int lane = tid & 31;
    const int warp = tid >> 5;
    const int g    = lane >> 2;
    const int tg   = lane & 3;
    const int wm   = (warp >> 2) * 64;
    const int wn   = (warp & 3) * 32;
    const int m0   = blockIdx.y * 128;
    const int n0   = blockIdx.x * 128;

    const int ldr = tid >> 3;
    const int ldb = tid & 7;

    // ldmatrix per-lane constants
    const int l7  = lane & 7;
    const int rA8 = ((lane >> 3) & 1) * 8;   // A: lanes 8-15,24-31 -> rows+8
    const int gA  = lane >> 4;               // A: lanes 16-31 -> granule+1
    const int rB8 = (lane >> 4) * 8;         // B: lanes 16-31 -> rows+8
    const int gB  = (lane >> 3) & 1;         // B: lanes 8-15,24-31 -> granule+1

    // per-lane byte row offsets (within a stage)
    uint32_t arow[4], brow[2];
#pragma unroll
    for (int mt = 0; mt < 4; mt++) arow[mt] = (wm + mt * 16 + rA8 + l7) * 128u;
#pragma unroll
    for (int np = 0; np < 2; np++) brow[np] = (wn + np * 16 + rB8 + l7) * 128u;

    uint32_t AbS[3], BbS[3];
#pragma unroll
    for (int s = 0; s < 3; s++) {
        AbS[s] = smem_u32(Asm + s * G_STAGE);
        BbS[s] = smem_u32(Bsm + s * G_STAGE);
    }

    float c[4][4][4];
#pragma unroll
    for (int mt = 0; mt < 4; mt++)
#pragma unroll
        for (int nt = 0; nt < 4; nt++)
#pragma unroll
            for (int i = 0; i < 4; i++) c[mt][nt][i] = 0.0f;

    const int nIter = K >> 5;

    auto load_chunk = [&](int s, int ch) {
        float* As = Asm + s * G_STAGE;
        float* Bs = Bsm + s * G_STAGE;
        const int k0 = ch << 5;
#pragma unroll
        for (int i = 0; i < 4; i++) {
            int r  = ldr + i * 32;
            int sc = ((ldb ^ (r & 7)) << 2);
            cp16(&As[r * 32 + sc], &A[(size_t)(m0 + r) * K + k0 + ldb * 4]);
            cp16(&Bs[r * 32 + sc], &B[(size_t)(n0 + r) * K + k0 + ldb * 4]);
        }
        cp_commit();
    };

    load_chunk(0, 0);
    load_chunk(1, 1);

#pragma unroll 1
    for (int it = 0; it < nIter; it++) {
        if (it + 1 < nIter) cp_wait<1>(); else cp_wait<0>();
        __syncthreads();
        if (it + 2 < nIter) load_chunk((it + 2) % 3, it + 2);

        const int st = it % 3;
        const uint32_t Ab = AbS[st];
        const uint32_t Bb = BbS[st];
#pragma unroll
        for (int k8 = 0; k8 < 4; k8++) {
            const uint32_t swA = (uint32_t)(((2 * k8 + gA) ^ l7) << 4);
            const uint32_t swB = (uint32_t)(((2 * k8 + gB) ^ l7) << 4);
            unsigned a[4][4], b[4][2];
#pragma unroll
            for (int mt = 0; mt < 4; mt++)
                ldsm4(a[mt][0], a[mt][1], a[mt][2], a[mt][3], Ab + arow[mt] + swA);
            ldsm4(b[0][0], b[0][1], b[1][0], b[1][1], Bb + brow[0] + swB);
            ldsm4(b[2][0], b[2][1], b[3][0], b[3][1], Bb + brow[1] + swB);
#pragma unroll
            for (int mt = 0; mt < 4; mt++)
#pragma unroll
                for (int nt = 0; nt < 4; nt++)
                    mma_tf32(c[mt][nt], a[mt], b[nt][0], b[nt][1]);
        }
    }

#pragma unroll
    for (int mt = 0; mt < 4; mt++)
#pragma unroll
        for (int nt = 0; nt < 4; nt++) {
            int row = m0 + wm + mt * 16 + g;
            int col = n0 + wn + nt * 8 + tg * 2;
            float v0 = c[mt][nt][0], v1 = c[mt][nt][1];
            float v2 = c[mt][nt][2], v3 = c[mt][nt][3];
            if (ROUND) {
                v0 = __uint_as_float(f2tf(v0));
                v1 = __uint_as_float(f2tf(v1));
                v2 = __uint_as_float(f2tf(v2));
                v3 = __uint_as_float(f2tf(v3));
            }
            *(float2*)&C[(size_t)row * N + col]       = make_float2(v0, v1);
            *(float2*)&C[(size_t)(row + 8) * N + col] = make_float2(v2, v3);
        }
}

// ----------------------------------------------------------------------------
// Flash attention (causal), tf32 mma, 2-stage cp.async, occ=2.
// ONE barrier per kt; warp-level skip of fully-masked tiles (min-row mask guard).
// K/P/Q fragment loads via ldmatrix.x4; V stays LDS (transposed pattern).
// ----------------------------------------------------------------------------
#define QP_PAD 68
#define K_PAD  68
#define V_PAD  72
#define K_STAGE (64 * K_PAD)
#define V_STAGE (64 * V_PAD)
#define ATTN_SMEM ((128 * QP_PAD + 2 * K_STAGE + 2 * V_STAGE) * 4)

__device__ __forceinline__ void attn_prefetch(float* Ks, float* Vs,
                                              const float* __restrict__ qkv,
                                              size_t tok0, int h, int kt,
                                              int stage, int tid) {
#pragma unroll
    for (int i = 0; i < 4; i++) {
        int idx = tid + i * 256;
        int r   = idx >> 4;
        int c4  = (idx & 15) * 4;
        const float* base = &qkv[(tok0 + kt * 64 + r) * (size_t)QKVN + h * HD + c4];
        cp16(&Ks[stage * K_STAGE + r * K_PAD + c4], base + DIM);
        cp16(&Vs[stage * V_STAGE + r * V_PAD + c4], base + 2 * DIM);
    }
    cp_commit();
}

__global__ void __launch_bounds__(256, 2)
attn_tf32_kernel(const float* __restrict__ qkv, float* __restrict__ att) {
    extern __shared__ float smf[];
    float* Qs = smf;                          // [128][QP_PAD]; reused as Ps
    float* Ks = smf + 128 * QP_PAD;           // [2][64][K_PAD]
    float* Vs = Ks + 2 * K_STAGE;             // [2][64][V_PAD]

    const int tid  = threadIdx.x;
    const int lane = tid & 31;
    const int warp = tid >> 5;
    const int g    = lane >> 2;
    const int tg   = lane & 3;
    const int bq   = gridDim.x - 1 - blockIdx.x;   // largest tiles first
    const int bh   = blockIdx.y;
    const int b    = bh >> 4;
    const int h    = bh & 15;
    const size_t tok0 = (size_t)b * SEQ;
    const int qr   = warp * 16;

    // ldmatrix per-lane constants (same mapping as GEMM)
    const int l7  = lane & 7;
    const int rA8 = ((lane >> 3) & 1) * 8;
    const int gA  = lane >> 4;
    const int rB8 = (lane >> 4) * 8;
    const int gB  = (lane >> 3) & 1;

    const int ktmax = 2 * bq + 2;

    attn_prefetch(Ks, Vs, qkv, tok0, h, 0, 0, tid);

    // Q: pre-rounded; *0.125 is exact
#pragma unroll
    for (int i = 0; i < 8; i++) {
        int idx = tid + i * 256;
        int r   = idx >> 4;
        int c4  = (idx & 15) * 4;
        float4 v = *(const float4*)&qkv[(tok0 + bq * 128 + r) * QKVN + h * HD + c4];
        Qs[r * QP_PAD + c4 + 0] = v.x * 0.125f;
        Qs[r * QP_PAD + c4 + 1] = v.y * 0.125f;
        Qs[r * QP_PAD + c4 + 2] = v.z * 0.125f;
        Qs[r * QP_PAD + c4 + 3] = v.w * 0.125f;
    }
    __syncthreads();

    // Hoist Q fragments via ldmatrix (A-pattern, 272B row stride, granule-aligned)
    unsigned qf[8][4];
    {
        const uint32_t qrow = smem_u32(Qs) + (qr + rA8 + l7) * (QP_PAD * 4u) + gA * 16u;
#pragma unroll
        for (int k8 = 0; k8 < 8; k8++)
            ldsm4(qf[k8][0], qf[k8][1], qf[k8][2], qf[k8][3], qrow + k8 * 32u);
    }
    __syncthreads();

    unsigned* Ps = (unsigned*)Qs;
    // P fragment base (A-pattern) and K row bases (B-pattern)
    const uint32_t prow = smem_u32(Ps) + (qr + rA8 + l7) * (QP_PAD * 4u) + gA * 16u;
    uint32_t krow[4];
#pragma unroll
    for (int np = 0; np < 4; np++)
        krow[np] = smem_u32(Ks) + (np * 16 + rB8 + l7) * (K_PAD * 4u) + gB * 16u;

    float oacc[8][4];
#pragma unroll
    for (int n = 0; n < 8; n++)
#pragma unroll
        for (int i = 0; i < 4; i++) oacc[n][i] = 0.0f;
    float mrow[2] = {-INFINITY, -INFINITY};
    float lrow[2] = {0.0f, 0.0f};

    const int r0g = bq * 128 + qr + g;
    const int r1g = r0g + 8;
    const int warp_row_min = bq * 128 + qr;
    const int warp_row_max = warp_row_min + 15;

#pragma unroll 1
    for (int kt = 0; kt < ktmax; kt++) {
        cp_wait<0>();
        __syncthreads();   // all warps done with iter kt-1 -> stage (kt+1)&1 free
        if (kt + 1 < ktmax)
            attn_prefetch(Ks, Vs, qkv, tok0, h, kt + 1, (kt + 1) & 1, tid);

        // Fully-masked tile for this warp contributes 0 — skip.
        if (warp_row_max < kt * 64) continue;

        const uint32_t kstage = (uint32_t)((kt & 1) * K_STAGE * 4);
        const unsigned* Vst = (const unsigned*)(Vs + (kt & 1) * V_STAGE);

        float sacc[8][4];
#pragma unroll
        for (int n = 0; n < 8; n++)
#pragma unroll
            for (int i = 0; i < 4; i++) sacc[n][i] = 0.0f;
#pragma unroll
        for (int k8 = 0; k8 < 8; k8++) {
#pragma unroll
            for (int np = 0; np < 4; np++) {
                unsigned b0, b1, b2, b3;
                ldsm4(b0, b1, b2, b3, krow[np] + kstage + k8 * 32u);
                mma_tf32(sacc[2 * np],     qf[k8], b0, b1);
                mma_tf32(sacc[2 * np + 1], qf[k8], b2, b3);
            }
        }

        // Mask iff tile max col can exceed warp MIN row (diagonal intersects).
        if (kt * 64 + 63 > warp_row_min) {
#pragma unroll
            for (int n = 0; n < 8; n++) {
#pragma unroll
                for (int ci = 0; ci < 4; ci++) {
                    int col = kt * 64 + n * 8 + tg * 2 + (ci & 1);
                    int rowg = (ci < 2) ? r0g : r1g;
                    if (col > rowg) sacc[n][ci] = -INFINITY;
                }
            }
        }

        float mx0 = -INFINITY, mx1 = -INFINITY;
#pragma unroll
        for (int n = 0; n < 8; n++) {
            mx0 = fmaxf(mx0, fmaxf(sacc[n][0], sacc[n][1]));
            mx1 = fmaxf(mx1, fmaxf(sacc[n][2], sacc[n][3]));
        }
#pragma unroll
        for (int off = 1; off <= 2; off <<= 1) {
            mx0 = fmaxf(mx0, __shfl_xor_sync(0xffffffffu, mx0, off));
            mx1 = fmaxf(mx1, __shfl_xor_sync(0xffffffffu, mx1, off));
        }
        float mn0 = fmaxf(mrow[0], mx0);
        float mn1 = fmaxf(mrow[1], mx1);
        float al0 = __expf(mrow[0] - mn0);
        float al1 = __expf(mrow[1] - mn1);

        float rs0 = 0.0f, rs1 = 0.0f;
#pragma unroll
        for (int n = 0; n < 8; n++) {
            sacc[n][0] = __expf(sacc[n][0] - mn0);
            sacc[n][1] = __expf(sacc[n][1] - mn0);
            sacc[n][2] = __expf(sacc[n][2] - mn1);
            sacc[n][3] = __expf(sacc[n][3] - mn1);
            rs0 += sacc[n][0] + sacc[n][1];
            rs1 += sacc[n][2] + sacc[n][3];
        }
#pragma unroll
        for (int off = 1; off <= 2; off <<= 1) {
            rs0 += __shfl_xor_sync(0xffffffffu, rs0, off);
            rs1 += __shfl_xor_sync(0xffffffffu, rs1, off);
        }
        lrow[0] = lrow[0] * al0 + rs0;
        lrow[1] = lrow[1] * al1 + rs1;
        mrow[0] = mn0;
        mrow[1] = mn1;
#pragma unroll
        for (int n = 0; n < 8; n++) {
            oacc[n][0] *= al0; oacc[n][1] *= al0;
            oacc[n][2] *= al1; oacc[n][3] *= al1;
        }

#pragma unroll
        for (int n = 0; n < 8; n++) {
            *(uint2*)&Ps[(qr + g) * QP_PAD + n * 8 + tg * 2] =
                make_uint2(f2tf(sacc[n][0]), f2tf(sacc[n][1]));
            *(uint2*)&Ps[(qr + g + 8) * QP_PAD + n * 8 + tg * 2] =
                make_uint2(f2tf(sacc[n][2]), f2tf(sacc[n][3]));
        }
        __syncwarp();

#pragma unroll
        for (int k8 = 0; k8 < 8; k8++) {
            int kc = k8 * 8;
            unsigned pa[4];
            ldsm4(pa[0], pa[1], pa[2], pa[3], prow + k8 * 32u);
#pragma unroll
            for (int n = 0; n < 8; n++) {
                unsigned b0 = Vst[(kc + tg) * V_PAD + n * 8 + g];
                unsigned b1 = Vst[(kc + tg + 4) * V_PAD + n * 8 + g];
                mma_tf32(oacc[n], pa, b0, b1);
            }
        }
    }

    float inv0 = 1.0f / lrow[0];
    float inv1 = 1.0f / lrow[1];
    size_t row0 = tok0 + bq * 128 + qr + g;
#pragma unroll
    for (int n = 0; n < 8; n++) {
        int col = h * HD + n * 8 + tg * 2;
        *(float2*)&att[row0 * DIM + col] =
            make_float2(__uint_as_float(f2tf(oacc[n][0] * inv0)),
                        __uint_as_float(f2tf(oacc[n][1] * inv0)));
        *(float2*)&att[(row0 + 8) * DIM + col] =
            make_float2(__uint_as_float(f2tf(oacc[n][2] * inv1)),
                        __uint_as_float(f2tf(oacc[n][3] * inv1)));
    }
}

// ----------------------------------------------------------------------------
extern "C" void kernel_launch(void* const* d_in, const int* in_sizes, int n_in,
                              void* d_out, int out_size) {
    const float* x     = (const float*)d_in[0];
    const float* W_qkv = (const float*)d_in[1];
    const float* W_out = (const float*)d_in[2];
    float* out = (float*)d_out;

    float *qkv_buf, *att_buf, *xr, *wqr, *wor;
    cudaGetSymbolAddress((void**)&qkv_buf, g_qkv);
    cudaGetSymbolAddress((void**)&att_buf, g_att);
    cudaGetSymbolAddress((void**)&xr,  g_xr);
    cudaGetSymbolAddress((void**)&wqr, g_wqr);
    cudaGetSymbolAddress((void**)&wor, g_wor);

    cudaFuncSetAttribute(gemm_tf32_kernel<true>,
                         cudaFuncAttributeMaxDynamicSharedMemorySize, GEMM_SMEM);
    cudaFuncSetAttribute(gemm_tf32_kernel<false>,
                         cudaFuncAttributeMaxDynamicSharedMemorySize, GEMM_SMEM);
    cudaFuncSetAttribute(attn_tf32_kernel,
                         cudaFuncAttributeMaxDynamicSharedMemorySize, ATTN_SMEM);

    // 0) One-time rounding pre-pass
    {
        int n4x = MTOK * DIM / 4;
        round_tf32_kernel<<<(n4x + 255) / 256, 256>>>(x, xr, n4x);
        int n4q = QKVN * DIM / 4;
        round_tf32_kernel<<<(n4q + 255) / 256, 256>>>(W_qkv, wqr, n4q);
        int n4o = DIM * DIM / 4;
        round_tf32_kernel<<<(n4o + 255) / 256, 256>>>(W_out, wor, n4o);
    }

    // 1) QKV projection
    {
        dim3 grid(QKVN / 128, MTOK / 128);
        gemm_tf32_kernel<true><<<grid, 256, GEMM_SMEM>>>(xr, wqr, qkv_buf, MTOK, QKVN, DIM);
    }
    // 2) Causal flash attention
    {
        dim3 grid(SEQ / 128, BSZ * NH);
        attn_tf32_kernel<<<grid, 256, ATTN_SMEM>>>(qkv_buf, att_buf);
    }
    // 3) Output projection
    {
        dim3 grid(DIM / 128, MTOK / 128);
        gemm_tf32_kernel<false><<<grid, 256, GEMM_SMEM>>>(att_buf, wor, out, MTOK, DIM, DIM);
    }
}